// round 11
// baseline (speedup 1.0000x reference)
#include <cuda_runtime.h>
#include <cuda_bf16.h>
#include <cuda_fp16.h>
#include <cstdint>

// Scratch (allocation-free rule: __device__ globals)
__device__ float    g_qkv[4 * 384 * 2304];  // (b,384,N): q=0..127, k=128..255
__device__ uint32_t g_vbf[4 * 128 * 1152];  // V packed bf16x2 key-pairs: [b][vch][keypair]
__device__ float    g_attn[4 * 128 * 2304]; // (b,8,N,16) contiguous == (b,128,N) reinterpret
__device__ uint32_t g_w[9 * 2 * 4 * 4096];  // conv weights fp16x2: [tap][half][ocg][4096]

#define N_SP 2304   // 48*48

__device__ __forceinline__ uint32_t to_tf32(float f) {
    uint32_t t;
    asm("cvt.rna.tf32.f32 %0, %1;" : "=r"(t) : "f"(f));
    return t;
}

__device__ __forceinline__ float fast_ex2(float v) {
    float r;
    asm("ex2.approx.ftz.f32 %0, %1;" : "=f"(r) : "f"(v));
    return r;
}

__device__ __forceinline__ uint32_t pack_bf16(float hi, float lo) {
    uint32_t r;
    asm("cvt.rn.bf16x2.f32 %0, %1, %2;" : "=r"(r) : "f"(hi), "f"(lo));
    return r;
}

__device__ __forceinline__ uint32_t pack_f16(float hi, float lo) {
    uint32_t r;
    asm("cvt.rn.f16x2.f32 %0, %1, %2;" : "=r"(r) : "f"(hi), "f"(lo));
    return r;
}

__device__ __forceinline__ void mma_tf32(float c[4], const uint32_t a[4],
                                         uint32_t b0, uint32_t b1)
{
    asm volatile(
        "mma.sync.aligned.m16n8k8.row.col.f32.tf32.tf32.f32 "
        "{%0,%1,%2,%3}, {%4,%5,%6,%7}, {%8,%9}, {%0,%1,%2,%3};"
        : "+f"(c[0]), "+f"(c[1]), "+f"(c[2]), "+f"(c[3])
        : "r"(a[0]), "r"(a[1]), "r"(a[2]), "r"(a[3]), "r"(b0), "r"(b1));
}

__device__ __forceinline__ void mma_f16(float c[4], uint4 a,
                                        uint32_t b0, uint32_t b1)
{
    asm volatile(
        "mma.sync.aligned.m16n8k16.row.col.f32.f16.f16.f32 "
        "{%0,%1,%2,%3}, {%4,%5,%6,%7}, {%8,%9}, {%0,%1,%2,%3};"
        : "+f"(c[0]), "+f"(c[1]), "+f"(c[2]), "+f"(c[3])
        : "r"(a.x), "r"(a.y), "r"(a.z), "r"(a.w), "r"(b0), "r"(b1));
}

__device__ __forceinline__ void mma_bf16(float c[4], const uint32_t a[4],
                                         uint32_t b0, uint32_t b1)
{
    asm volatile(
        "mma.sync.aligned.m16n8k16.row.col.f32.bf16.bf16.f32 "
        "{%0,%1,%2,%3}, {%4,%5,%6,%7}, {%8,%9}, {%0,%1,%2,%3};"
        : "+f"(c[0]), "+f"(c[1]), "+f"(c[2]), "+f"(c[3])
        : "r"(a[0]), "r"(a[1]), "r"(a[2]), "r"(a[3]), "r"(b0), "r"(b1));
}

__device__ __forceinline__ void cp_async16(uint32_t smem_addr, const void* gptr) {
    asm volatile("cp.async.cg.shared.global [%0], [%1], 16;"
                 :: "r"(smem_addr), "l"(gptr));
}
#define CP_COMMIT() asm volatile("cp.async.commit_group;" ::: "memory")
#define CP_WAIT0()  asm volatile("cp.async.wait_group 0;" ::: "memory")

// ---------------------------------------------------------------------------
// Kernel 0: pack conv weights as fp16x2 ic-pairs in m16n8k16 A-frag order.
// Chunk (16KB = 4096 u32) = (tap, half, ocg): [ob 8][icclo 4][lane 32][e 4]
// ---------------------------------------------------------------------------
__global__ __launch_bounds__(1024) void wprep_kernel(
    const float* __restrict__ w_init, const float* __restrict__ w_qkv)
{
    int idx = blockIdx.x * 1024 + threadIdx.x;   // 294912 total
    int e     = idx & 3;
    int lane  = (idx >> 2) & 31;
    int icclo = (idx >> 7) & 3;
    int ob    = (idx >> 9) & 7;
    int ocg   = (idx >> 12) & 3;
    int half  = (idx >> 14) & 1;
    int tap   = idx >> 15;
    int g = lane >> 2, q = lane & 3;
    int icc = half * 4 + icclo;
    int oc = ocg * 128 + ob * 16 + g + (e & 1) * 8;
    int ic = icc * 16 + 2 * q + ((e >> 1) & 1) * 8;
    float w0, w1;
    if (oc < 128) {
        w0 = w_init[(oc * 128 + ic) * 9 + tap];
        w1 = w_init[(oc * 128 + ic + 1) * 9 + tap];
    } else {
        w0 = w_qkv[((oc - 128) * 128 + ic) * 9 + tap];
        w1 = w_qkv[((oc - 128) * 128 + ic + 1) * 9 + tap];
    }
    g_w[idx] = pack_f16(w1, w0);
}

// ---------------------------------------------------------------------------
// Kernel 1: 3x3 circular conv, fp16 mma implicit GEMM.
// ONE output row per CTA (768 CTAs -> staggered waves, small tail).
// CTA = 128 oc x 48 pos; 8 warps = 4(oc) x 2(col-half of 24).
// x-tile: 3 halo rows of 64 icpairs (43KB) + 2x16KB weight buffers = 75KB.
// ---------------------------------------------------------------------------
#define XS_STRIDE 56                      // u32 per (row, icpair) line
#define XS_U32 (3 * 64 * XS_STRIDE)       // 10752 u32 = 43008 B
#define WCHUNK 4096                       // u32 per weight chunk (16 KB)

__global__ __launch_bounds__(256, 2) void conv_mma_kernel(
    const float* __restrict__ x, float* __restrict__ out)
{
    extern __shared__ uint32_t smu[];
    uint32_t* x_s = smu;                  // [3 rows][64 icpair][56]
    uint32_t* w_s = smu + XS_U32;         // [2][4096]

    const int b    = blockIdx.z;
    const int orow = blockIdx.y;          // output row 0..47
    const int ocg  = blockIdx.x;
    const int tid  = threadIdx.x;
    const int wid = tid >> 5, lane = tid & 31;
    const int warp_m  = wid & 3;          // oc group of 32
    const int warp_ch = wid >> 2;         // column half (24 cols)
    const int g = lane >> 2, q = lane & 3;

    const uint32_t ws_u32 = (uint32_t)__cvta_generic_to_shared(w_s);

    // chunk c (0..17): tap = c>>1, half = c&1
    auto stage_w = [&](int c) {
        const float4* src = (const float4*)(g_w + ((size_t)c * 4 + ocg) * WCHUNK);
        uint32_t dst = ws_u32 + (uint32_t)(c & 1) * (WCHUNK * 4);
        #pragma unroll
        for (int i = 0; i < 4; i++) {
            int e4 = tid + i * 256;       // 1024 float4
            cp_async16(dst + e4 * 16, src + e4);
        }
    };

    stage_w(0); CP_COMMIT();

    // stage x: 3 halo rows x 64 icpairs = 192 lines; threads 0..191
    if (tid < 192) {
        int r = tid >> 6, icp = tid & 63;
        int srow = (orow - 1 + r + 48) % 48;
        const float* s0 = x + ((b * 128 + 2 * icp) * 48 + srow) * 48;
        const float* s1 = s0 + 2304;      // next ic row
        uint32_t* dst = &x_s[(r * 64 + icp) * XS_STRIDE];
        #pragma unroll
        for (int t = 0; t < 48; t++)
            dst[2 + t] = pack_f16(s1[t], s0[t]);
        dst[1]  = pack_f16(s1[47], s0[47]);
        dst[50] = pack_f16(s1[0],  s0[0]);
    }

    float c_acc[2][3][4];
    #pragma unroll
    for (int mi = 0; mi < 2; mi++)
        #pragma unroll
        for (int j = 0; j < 3; j++)
            #pragma unroll
            for (int t = 0; t < 4; t++) c_acc[mi][j][t] = 0.f;

    for (int c = 0; c < 18; c++) {
        CP_WAIT0();
        __syncthreads();
        if (c < 17) { stage_w(c + 1); CP_COMMIT(); }

        const int tap = c >> 1, half = c & 1;
        const int dr = tap / 3 - 1, dc = tap % 3 - 1;
        const int irow = dr + 1;          // 0..2
        const int colb = dc + 2 + g + warp_ch * 24;
        const uint32_t* xrow = x_s + irow * 64 * XS_STRIDE;
        const uint4* wbuf = (const uint4*)(w_s + (c & 1) * WCHUNK);

        #pragma unroll
        for (int icclo = 0; icclo < 4; icclo++) {
            const int icc = half * 4 + icclo;
            uint4 a0 = wbuf[((warp_m * 2 + 0) * 4 + icclo) * 32 + lane];
            uint4 a1 = wbuf[((warp_m * 2 + 1) * 4 + icclo) * 32 + lane];
            #pragma unroll
            for (int j = 0; j < 3; j++) {
                uint32_t b0 = xrow[(icc * 8 + q)     * XS_STRIDE + colb + j * 8];
                uint32_t b1 = xrow[(icc * 8 + q + 4) * XS_STRIDE + colb + j * 8];
                mma_f16(c_acc[0][j], a0, b0, b1);
                mma_f16(c_acc[1][j], a1, b0, b1);
            }
        }
    }

    const int spat = orow * 48 + warp_ch * 24;
    #pragma unroll
    for (int mi = 0; mi < 2; mi++) {
        int oc_l = ocg * 128 + warp_m * 32 + mi * 16 + g;
        if (oc_l < 384) {
            float* p = (oc_l < 128)
                ? out   + (size_t)(b * 256 + oc_l) * N_SP
                : g_qkv + (size_t)(b * 384 + oc_l - 128) * N_SP;
            float* p8 = p + 8 * N_SP;
            #pragma unroll
            for (int j = 0; j < 3; j++) {
                int col = j * 8 + 2 * q;
                *(float2*)&p [spat + col] = make_float2(c_acc[mi][j][0], c_acc[mi][j][1]);
                *(float2*)&p8[spat + col] = make_float2(c_acc[mi][j][2], c_acc[mi][j][3]);
            }
        } else {
            int vch = oc_l - 384;
            uint32_t* v0 = g_vbf + (size_t)(b * 128 + vch) * 1152
                         + orow * 24 + warp_ch * 12;
            uint32_t* v8 = v0 + 8 * 1152;
            #pragma unroll
            for (int j = 0; j < 3; j++) {
                v0[j * 4 + q] = pack_bf16(c_acc[mi][j][1], c_acc[mi][j][0]);
                v8[j * 4 + q] = pack_bf16(c_acc[mi][j][3], c_acc[mi][j][2]);
            }
        }
    }
}

// ---------------------------------------------------------------------------
// Kernel 2: flash attention. S: tf32 mma. PV: bf16 mma with C->A pass-through.
// (proven round-6 configuration)
// ---------------------------------------------------------------------------
#define KS_STRIDE 136    // K smem: [ch][key] fp32
#define VS2_STRIDE 68    // V smem: [dv][keypair] u32 bf16x2
#define KBUF (16 * KS_STRIDE)
#define VBUF (16 * VS2_STRIDE)

__global__ __launch_bounds__(256, 2) void attn_mma_kernel()
{
    extern __shared__ float sm[];
    float*    k_s = sm;                          // [2][16][136]
    uint32_t* v_s = (uint32_t*)(sm + 2 * KBUF);  // [2][16][68]

    const int b = blockIdx.z, h = blockIdx.y, qt = blockIdx.x;
    const int tid = threadIdx.x, wid = tid >> 5, lane = tid & 31;
    const int g = lane >> 2, q = lane & 3;
    const int qbase = qt * 128 + wid * 16;

    const float*    qptr = g_qkv + (size_t)(b * 384 + h * 16) * N_SP;
    const float*    kptr = g_qkv + (size_t)(b * 384 + 128 + h * 16) * N_SP;
    const uint32_t* vptr = g_vbf + (size_t)(b * 128 + h * 16) * 1152;

    const uint32_t ks_u32 = (uint32_t)__cvta_generic_to_shared(k_s);
    const uint32_t vs_u32 = (uint32_t)__cvta_generic_to_shared(v_s);

    auto stage = [&](int kt) {
        uint32_t buf = (uint32_t)(kt & 1);
        #pragma unroll
        for (int it = 0; it < 2; it++) {
            int i  = tid + it * 256;
            int ch = i >> 5, k4 = i & 31;
            cp_async16(ks_u32 + (buf * KBUF + ch * KS_STRIDE + k4 * 4) * 4,
                       kptr + ch * N_SP + kt * 128 + k4 * 4);
        }
        {
            int ch = tid >> 4, kp4 = tid & 15;
            cp_async16(vs_u32 + (buf * VBUF + ch * VS2_STRIDE + kp4 * 4) * 4,
                       vptr + ch * 1152 + kt * 64 + kp4 * 4);
        }
    };

    stage(0); CP_COMMIT();

    const float qscale = 0.25f * 1.4426950408889634f;  // dk^-0.5 * log2(e)
    uint32_t qa[2][4];
    #pragma unroll
    for (int s = 0; s < 2; s++) {
        qa[s][0] = to_tf32(qptr[(s * 8 + q)     * N_SP + qbase + g]     * qscale);
        qa[s][1] = to_tf32(qptr[(s * 8 + q)     * N_SP + qbase + g + 8] * qscale);
        qa[s][2] = to_tf32(qptr[(s * 8 + q + 4) * N_SP + qbase + g]     * qscale);
        qa[s][3] = to_tf32(qptr[(s * 8 + q + 4) * N_SP + qbase + g + 8] * qscale);
    }

    float sum_g = 0.f, sum_g8 = 0.f;
    float o[2][4];
    #pragma unroll
    for (int nt = 0; nt < 2; nt++)
        #pragma unroll
        for (int t = 0; t < 4; t++) o[nt][t] = 0.f;

    for (int kt = 0; kt < 18; kt++) {
        CP_WAIT0();
        __syncthreads();
        if (kt < 17) { stage(kt + 1); CP_COMMIT(); }

        const uint32_t* ks32 = (const uint32_t*)(k_s + (kt & 1) * KBUF);
        const uint32_t* vbuf = v_s + (kt & 1) * VBUF;

        #pragma unroll
        for (int kb = 0; kb < 8; kb++) {        // 16 keys per block
            float cs0[4] = {0.f, 0.f, 0.f, 0.f};
            float cs1[4] = {0.f, 0.f, 0.f, 0.f};
            #pragma unroll
            for (int s = 0; s < 2; s++) {
                int r0 = (s * 8 + q) * KS_STRIDE + kb * 16 + g;
                int r1 = (s * 8 + q + 4) * KS_STRIDE + kb * 16 + g;
                mma_tf32(cs0, qa[s], ks32[r0],     ks32[r1]);
                mma_tf32(cs1, qa[s], ks32[r0 + 8], ks32[r1 + 8]);
            }

            float p00 = fast_ex2(cs0[0]), p01 = fast_ex2(cs0[1]);
            float p02 = fast_ex2(cs0[2]), p03 = fast_ex2(cs0[3]);
            float p10 = fast_ex2(cs1[0]), p11 = fast_ex2(cs1[1]);
            float p12 = fast_ex2(cs1[2]), p13 = fast_ex2(cs1[3]);
            sum_g  += (p00 + p01) + (p10 + p11);
            sum_g8 += (p02 + p03) + (p12 + p13);

            uint32_t a[4];
            a[0] = pack_bf16(p01, p00);
            a[1] = pack_bf16(p03, p02);
            a[2] = pack_bf16(p11, p10);
            a[3] = pack_bf16(p13, p12);

            mma_bf16(o[0], a, vbuf[g * VS2_STRIDE + kb * 8 + q],
                              vbuf[g * VS2_STRIDE + kb * 8 + q + 4]);
            mma_bf16(o[1], a, vbuf[(8 + g) * VS2_STRIDE + kb * 8 + q],
                              vbuf[(8 + g) * VS2_STRIDE + kb * 8 + q + 4]);
        }
    }

    sum_g  += __shfl_xor_sync(0xffffffffu, sum_g, 1);
    sum_g  += __shfl_xor_sync(0xffffffffu, sum_g, 2);
    sum_g8 += __shfl_xor_sync(0xffffffffu, sum_g8, 1);
    sum_g8 += __shfl_xor_sync(0xffffffffu, sum_g8, 2);
    const float il_g = 1.f / sum_g, il_g8 = 1.f / sum_g8;

    const size_t nb = (size_t)(b * 8 + h) * N_SP;
    #pragma unroll
    for (int nt = 0; nt < 2; nt++) {
        float* d0 = g_attn + (nb + qbase + g)     * 16 + nt * 8 + 2 * q;
        float* d8 = g_attn + (nb + qbase + g + 8) * 16 + nt * 8 + 2 * q;
        *(float2*)d0 = make_float2(o[nt][0] * il_g,  o[nt][1] * il_g);
        *(float2*)d8 = make_float2(o[nt][2] * il_g8, o[nt][3] * il_g8);
    }
}

// ---------------------------------------------------------------------------
// Kernel 3: 1x1 projection, tf32 mma: C[128oc,64n] = W[128,128]*A[128,64n]
// ---------------------------------------------------------------------------
#define PW_STRIDE 132
#define PA_STRIDE 72

__global__ __launch_bounds__(256) void proj_mma_kernel(
    const float* __restrict__ w_out, float* __restrict__ out)
{
    extern __shared__ float smf[];
    float* w_s = smf;                   // [128][132]
    float* a_s = smf + 128 * PW_STRIDE; // [128][72]

    const int b  = blockIdx.y;
    const int n0 = blockIdx.x * 64;
    const int tid = threadIdx.x, wid = tid >> 5, lane = tid & 31;
    const int g = lane >> 2, q = lane & 3;

    const float4* wsrc = (const float4*)w_out;
    #pragma unroll
    for (int i = 0; i < 16; i++) {
        int e4 = tid + i * 256;
        int oc = e4 >> 5, ic4 = e4 & 31;
        *(float4*)&w_s[oc * PW_STRIDE + ic4 * 4] = wsrc[e4];
    }
    #pragma unroll
    for (int i = 0; i < 8; i++) {
        int e4 = tid + i * 256;
        int ic = e4 >> 4, c4 = e4 & 15;
        *(float4*)&a_s[ic * PA_STRIDE + c4 * 4] =
            *(const float4*)&g_attn[(size_t)(b * 128 + ic) * N_SP + n0 + c4 * 4];
    }
    __syncthreads();

    const uint32_t* ws = (const uint32_t*)w_s;
    const uint32_t* as = (const uint32_t*)a_s;

    float c[8][4];
    #pragma unroll
    for (int j = 0; j < 8; j++)
        #pragma unroll
        for (int t = 0; t < 4; t++) c[j][t] = 0.f;

    #pragma unroll
    for (int ks = 0; ks < 16; ks++) {
        uint32_t a[4];
        int r0 = (wid * 16 + g) * PW_STRIDE + ks * 8 + q;
        a[0] = ws[r0];
        a[1] = ws[r0 + 8 * PW_STRIDE];
        a[2] = ws[r0 + 4];
        a[3] = ws[r0 + 8 * PW_STRIDE + 4];
        #pragma unroll
        for (int j = 0; j < 8; j++) {
            uint32_t b0 = as[(ks * 8 + q)     * PA_STRIDE + j * 8 + g];
            uint32_t b1 = as[(ks * 8 + q + 4) * PA_STRIDE + j * 8 + g];
            mma_tf32(c[j], a, b0, b1);
        }
    }

    #pragma unroll
    for (int j = 0; j < 8; j++) {
        int oc  = wid * 16 + g;
        int col = n0 + j * 8 + 2 * q;
        float* p = out + (size_t)(b * 256 + 128 + oc) * N_SP;
        *(float2*)&p[col]            = make_float2(c[j][0], c[j][1]);
        *(float2*)&p[8 * N_SP + col] = make_float2(c[j][2], c[j][3]);
    }
}

// ---------------------------------------------------------------------------
extern "C" void kernel_launch(void* const* d_in, const int* in_sizes, int n_in,
                              void* d_out, int out_size)
{
    const float* x      = (const float*)d_in[0];
    const float* w_init = (const float*)d_in[1];
    const float* w_qkv  = (const float*)d_in[2];
    const float* w_out  = (const float*)d_in[3];
    float* out = (float*)d_out;

    const int conv_smem = (XS_U32 + 2 * WCHUNK) * 4;               // 75776 B
    const int attn_smem = (2 * KBUF) * 4 + (2 * VBUF) * 4;         // 26112 B
    const int proj_smem = (128 * PW_STRIDE + 128 * PA_STRIDE) * 4; // 104448 B
    cudaFuncSetAttribute(conv_mma_kernel,
                         cudaFuncAttributeMaxDynamicSharedMemorySize, conv_smem);
    cudaFuncSetAttribute(attn_mma_kernel,
                         cudaFuncAttributeMaxDynamicSharedMemorySize, attn_smem);
    cudaFuncSetAttribute(proj_mma_kernel,
                         cudaFuncAttributeMaxDynamicSharedMemorySize, proj_smem);

    wprep_kernel<<<288, 1024>>>(w_init, w_qkv);

    dim3 cg(4, 48, 4);
    conv_mma_kernel<<<cg, 256, conv_smem>>>(x, out);

    dim3 ag(18, 8, 4);
    attn_mma_kernel<<<ag, 256, attn_smem>>>();

    dim3 pg(36, 4);
    proj_mma_kernel<<<pg, 256, proj_smem>>>(w_out, out);
}

// round 12
// speedup vs baseline: 1.2189x; 1.2189x over previous
#include <cuda_runtime.h>
#include <cuda_bf16.h>
#include <cuda_fp16.h>
#include <cstdint>

// Scratch (allocation-free rule: __device__ globals)
__device__ float    g_qkv[4 * 384 * 2304];  // (b,384,N): q=0..127, k=128..255
__device__ uint32_t g_vbf[4 * 128 * 1152];  // V packed f16x2 key-pairs: [b][vch][keypair]
__device__ float    g_attn[4 * 128 * 2304]; // (b,8,N,16) contiguous == (b,128,N) reinterpret
__device__ uint32_t g_w[9 * 2 * 4 * 4096];  // conv weights fp16x2: [tap][half][ocg][4096]

#define N_SP 2304   // 48*48

__device__ __forceinline__ uint32_t to_tf32(float f) {
    uint32_t t;
    asm("cvt.rna.tf32.f32 %0, %1;" : "=r"(t) : "f"(f));
    return t;
}

__device__ __forceinline__ uint32_t pack_f16(float hi, float lo) {
    uint32_t r;
    asm("cvt.rn.f16x2.f32 %0, %1, %2;" : "=r"(r) : "f"(hi), "f"(lo));
    return r;
}

__device__ __forceinline__ uint32_t ex2_f16x2(uint32_t v) {
    uint32_t r;
    asm("ex2.approx.f16x2 %0, %1;" : "=r"(r) : "r"(v));
    return r;
}

__device__ __forceinline__ uint32_t hadd2(uint32_t a, uint32_t b) {
    uint32_t r;
    asm("add.rn.f16x2 %0, %1, %2;" : "=r"(r) : "r"(a), "r"(b));
    return r;
}

__device__ __forceinline__ void mma_tf32(float c[4], const uint32_t a[4],
                                         uint32_t b0, uint32_t b1)
{
    asm volatile(
        "mma.sync.aligned.m16n8k8.row.col.f32.tf32.tf32.f32 "
        "{%0,%1,%2,%3}, {%4,%5,%6,%7}, {%8,%9}, {%0,%1,%2,%3};"
        : "+f"(c[0]), "+f"(c[1]), "+f"(c[2]), "+f"(c[3])
        : "r"(a[0]), "r"(a[1]), "r"(a[2]), "r"(a[3]), "r"(b0), "r"(b1));
}

__device__ __forceinline__ void mma_f16v(float c[4], uint4 a,
                                         uint32_t b0, uint32_t b1)
{
    asm volatile(
        "mma.sync.aligned.m16n8k16.row.col.f32.f16.f16.f32 "
        "{%0,%1,%2,%3}, {%4,%5,%6,%7}, {%8,%9}, {%0,%1,%2,%3};"
        : "+f"(c[0]), "+f"(c[1]), "+f"(c[2]), "+f"(c[3])
        : "r"(a.x), "r"(a.y), "r"(a.z), "r"(a.w), "r"(b0), "r"(b1));
}

__device__ __forceinline__ void mma_f16a(float c[4], const uint32_t a[4],
                                         uint32_t b0, uint32_t b1)
{
    asm volatile(
        "mma.sync.aligned.m16n8k16.row.col.f32.f16.f16.f32 "
        "{%0,%1,%2,%3}, {%4,%5,%6,%7}, {%8,%9}, {%0,%1,%2,%3};"
        : "+f"(c[0]), "+f"(c[1]), "+f"(c[2]), "+f"(c[3])
        : "r"(a[0]), "r"(a[1]), "r"(a[2]), "r"(a[3]), "r"(b0), "r"(b1));
}

__device__ __forceinline__ void cp_async16(uint32_t smem_addr, const void* gptr) {
    asm volatile("cp.async.cg.shared.global [%0], [%1], 16;"
                 :: "r"(smem_addr), "l"(gptr));
}
#define CP_COMMIT() asm volatile("cp.async.commit_group;" ::: "memory")
#define CP_WAIT0()  asm volatile("cp.async.wait_group 0;" ::: "memory")

// ---------------------------------------------------------------------------
// Kernel 0: pack conv weights as fp16x2 ic-pairs in m16n8k16 A-frag order.
// Chunk (16KB = 4096 u32) = (tap, half, ocg): [ob 8][icclo 4][lane 32][e 4]
// ---------------------------------------------------------------------------
__global__ __launch_bounds__(1024) void wprep_kernel(
    const float* __restrict__ w_init, const float* __restrict__ w_qkv)
{
    int idx = blockIdx.x * 1024 + threadIdx.x;   // 294912 total
    int e     = idx & 3;
    int lane  = (idx >> 2) & 31;
    int icclo = (idx >> 7) & 3;
    int ob    = (idx >> 9) & 7;
    int ocg   = (idx >> 12) & 3;
    int half  = (idx >> 14) & 1;
    int tap   = idx >> 15;
    int g = lane >> 2, q = lane & 3;
    int icc = half * 4 + icclo;
    int oc = ocg * 128 + ob * 16 + g + (e & 1) * 8;
    int ic = icc * 16 + 2 * q + ((e >> 1) & 1) * 8;
    float w0, w1;
    if (oc < 128) {
        w0 = w_init[(oc * 128 + ic) * 9 + tap];
        w1 = w_init[(oc * 128 + ic + 1) * 9 + tap];
    } else {
        w0 = w_qkv[((oc - 128) * 128 + ic) * 9 + tap];
        w1 = w_qkv[((oc - 128) * 128 + ic + 1) * 9 + tap];
    }
    g_w[idx] = pack_f16(w1, w0);
}

// ---------------------------------------------------------------------------
// Kernel 1: 3x3 circular conv, fp16 mma implicit GEMM (R10 shape).
// 2 CTAs/SM (90KB). CTA = 128 oc x 96 pos (2 rows), 8 warps = 4(M) x 2(row).
// ---------------------------------------------------------------------------
#define XS_STRIDE 56                      // u32 per (row, icpair) line
#define XS_U32 (4 * 64 * XS_STRIDE)       // 14336 u32 = 57344 B
#define WCHUNK 4096                       // u32 per weight chunk (16 KB)

__global__ __launch_bounds__(256, 2) void conv_mma_kernel(
    const float* __restrict__ x, float* __restrict__ out)
{
    extern __shared__ uint32_t smu[];
    uint32_t* x_s = smu;                  // [4 rows][64 icpair][56]
    uint32_t* w_s = smu + XS_U32;         // [2][4096]

    const int b   = blockIdx.z;
    const int rp  = blockIdx.y;
    const int ocg = blockIdx.x;
    const int tid = threadIdx.x;
    const int wid = tid >> 5, lane = tid & 31;
    const int warp_m = wid & 3;
    const int warp_n = wid >> 2;
    const int g = lane >> 2, q = lane & 3;

    const uint32_t ws_u32 = (uint32_t)__cvta_generic_to_shared(w_s);

    // chunk c (0..17): tap = c>>1, half = c&1
    auto stage_w = [&](int c) {
        const float4* src = (const float4*)(g_w + ((size_t)c * 4 + ocg) * WCHUNK);
        uint32_t dst = ws_u32 + (uint32_t)(c & 1) * (WCHUNK * 4);
        #pragma unroll
        for (int i = 0; i < 4; i++) {
            int e4 = tid + i * 256;       // 1024 float4
            cp_async16(dst + e4 * 16, src + e4);
        }
    };

    stage_w(0); CP_COMMIT();

    // stage x: 256 (row, icpair) lines, one per thread, fp16x2-packed
    {
        int r = tid >> 6, icp = tid & 63;
        int srow = (2 * rp - 1 + r + 48) % 48;
        const float* s0 = x + ((b * 128 + 2 * icp) * 48 + srow) * 48;
        const float* s1 = s0 + 2304;      // next ic row
        uint32_t* dst = &x_s[(r * 64 + icp) * XS_STRIDE];
        #pragma unroll
        for (int t = 0; t < 48; t++)
            dst[2 + t] = pack_f16(s1[t], s0[t]);
        dst[1]  = pack_f16(s1[47], s0[47]);
        dst[50] = pack_f16(s1[0],  s0[0]);
    }

    float c_acc[2][6][4];
    #pragma unroll
    for (int mi = 0; mi < 2; mi++)
        #pragma unroll
        for (int j = 0; j < 6; j++)
            #pragma unroll
            for (int t = 0; t < 4; t++) c_acc[mi][j][t] = 0.f;

    for (int c = 0; c < 18; c++) {
        CP_WAIT0();
        __syncthreads();
        if (c < 17) { stage_w(c + 1); CP_COMMIT(); }

        const int tap = c >> 1, half = c & 1;
        const int dr = tap / 3 - 1, dc = tap % 3 - 1;
        const int irow = warp_n + dr + 1;
        const int colb = dc + 2 + g;
        const uint32_t* xrow = x_s + irow * 64 * XS_STRIDE;
        const uint4* wbuf = (const uint4*)(w_s + (c & 1) * WCHUNK);

        #pragma unroll
        for (int icclo = 0; icclo < 4; icclo++) {
            const int icc = half * 4 + icclo;
            uint4 a0 = wbuf[((warp_m * 2 + 0) * 4 + icclo) * 32 + lane];
            uint4 a1 = wbuf[((warp_m * 2 + 1) * 4 + icclo) * 32 + lane];
            #pragma unroll
            for (int j = 0; j < 6; j++) {
                uint32_t b0 = xrow[(icc * 8 + q)     * XS_STRIDE + colb + j * 8];
                uint32_t b1 = xrow[(icc * 8 + q + 4) * XS_STRIDE + colb + j * 8];
                mma_f16v(c_acc[0][j], a0, b0, b1);
                mma_f16v(c_acc[1][j], a1, b0, b1);
            }
        }
    }

    const int orow = 2 * rp + warp_n;
    const int spat = orow * 48;
    #pragma unroll
    for (int mi = 0; mi < 2; mi++) {
        int oc_l = ocg * 128 + warp_m * 32 + mi * 16 + g;
        if (oc_l < 384) {
            float* p = (oc_l < 128)
                ? out   + (size_t)(b * 256 + oc_l) * N_SP
                : g_qkv + (size_t)(b * 384 + oc_l - 128) * N_SP;
            float* p8 = p + 8 * N_SP;
            #pragma unroll
            for (int j = 0; j < 6; j++) {
                int col = j * 8 + 2 * q;
                *(float2*)&p [spat + col] = make_float2(c_acc[mi][j][0], c_acc[mi][j][1]);
                *(float2*)&p8[spat + col] = make_float2(c_acc[mi][j][2], c_acc[mi][j][3]);
            }
        } else {
            int vch = oc_l - 384;
            uint32_t* v0 = g_vbf + (size_t)(b * 128 + vch) * 1152 + orow * 24;
            uint32_t* v8 = v0 + 8 * 1152;
            #pragma unroll
            for (int j = 0; j < 6; j++) {
                v0[j * 4 + q] = pack_f16(c_acc[mi][j][1], c_acc[mi][j][0]);
                v8[j * 4 + q] = pack_f16(c_acc[mi][j][3], c_acc[mi][j][2]);
            }
        }
    }
}

// ---------------------------------------------------------------------------
// Kernel 2: flash attention. S: tf32 mma. Softmax: ex2.approx.f16x2 (2 exps
// per MUFU op), output feeds f16 PV mma directly. No-max softmax.
// ---------------------------------------------------------------------------
#define KS_STRIDE 136    // K smem: [ch][key] fp32
#define VS2_STRIDE 68    // V smem: [dv][keypair] u32 f16x2
#define KBUF (16 * KS_STRIDE)
#define VBUF (16 * VS2_STRIDE)

__global__ __launch_bounds__(256, 2) void attn_mma_kernel()
{
    extern __shared__ float sm[];
    float*    k_s = sm;                          // [2][16][136]
    uint32_t* v_s = (uint32_t*)(sm + 2 * KBUF);  // [2][16][68]

    const int b = blockIdx.z, h = blockIdx.y, qt = blockIdx.x;
    const int tid = threadIdx.x, wid = tid >> 5, lane = tid & 31;
    const int g = lane >> 2, q = lane & 3;
    const int qbase = qt * 128 + wid * 16;

    const float*    qptr = g_qkv + (size_t)(b * 384 + h * 16) * N_SP;
    const float*    kptr = g_qkv + (size_t)(b * 384 + 128 + h * 16) * N_SP;
    const uint32_t* vptr = g_vbf + (size_t)(b * 128 + h * 16) * 1152;

    const uint32_t ks_u32 = (uint32_t)__cvta_generic_to_shared(k_s);
    const uint32_t vs_u32 = (uint32_t)__cvta_generic_to_shared(v_s);

    auto stage = [&](int kt) {
        uint32_t buf = (uint32_t)(kt & 1);
        #pragma unroll
        for (int it = 0; it < 2; it++) {
            int i  = tid + it * 256;
            int ch = i >> 5, k4 = i & 31;
            cp_async16(ks_u32 + (buf * KBUF + ch * KS_STRIDE + k4 * 4) * 4,
                       kptr + ch * N_SP + kt * 128 + k4 * 4);
        }
        {
            int ch = tid >> 4, kp4 = tid & 15;
            cp_async16(vs_u32 + (buf * VBUF + ch * VS2_STRIDE + kp4 * 4) * 4,
                       vptr + ch * 1152 + kt * 64 + kp4 * 4);
        }
    };

    stage(0); CP_COMMIT();

    const float qscale = 0.25f * 1.4426950408889634f;  // dk^-0.5 * log2(e)
    uint32_t qa[2][4];
    #pragma unroll
    for (int s = 0; s < 2; s++) {
        qa[s][0] = to_tf32(qptr[(s * 8 + q)     * N_SP + qbase + g]     * qscale);
        qa[s][1] = to_tf32(qptr[(s * 8 + q)     * N_SP + qbase + g + 8] * qscale);
        qa[s][2] = to_tf32(qptr[(s * 8 + q + 4) * N_SP + qbase + g]     * qscale);
        qa[s][3] = to_tf32(qptr[(s * 8 + q + 4) * N_SP + qbase + g + 8] * qscale);
    }

    float sum_g = 0.f, sum_g8 = 0.f;
    float o[2][4];
    #pragma unroll
    for (int nt = 0; nt < 2; nt++)
        #pragma unroll
        for (int t = 0; t < 4; t++) o[nt][t] = 0.f;

    for (int kt = 0; kt < 18; kt++) {
        CP_WAIT0();
        __syncthreads();
        if (kt < 17) { stage(kt + 1); CP_COMMIT(); }

        const uint32_t* ks32 = (const uint32_t*)(k_s + (kt & 1) * KBUF);
        const uint32_t* vbuf = v_s + (kt & 1) * VBUF;

        uint32_t sg2 = 0, sg82 = 0;             // f16x2 partial sums (this kt)

        #pragma unroll
        for (int kb = 0; kb < 8; kb++) {        // 16 keys per block
            float cs0[4] = {0.f, 0.f, 0.f, 0.f};
            float cs1[4] = {0.f, 0.f, 0.f, 0.f};
            #pragma unroll
            for (int s = 0; s < 2; s++) {
                int r0 = (s * 8 + q) * KS_STRIDE + kb * 16 + g;
                int r1 = (s * 8 + q + 4) * KS_STRIDE + kb * 16 + g;
                mma_tf32(cs0, qa[s], ks32[r0],     ks32[r1]);
                mma_tf32(cs1, qa[s], ks32[r0 + 8], ks32[r1 + 8]);
            }

            // pack logit pairs -> 2-exps-per-MUFU -> f16 PV A-fragment
            uint32_t a[4];
            a[0] = ex2_f16x2(pack_f16(cs0[1], cs0[0]));  // rows g,   cols 2q,2q+1
            a[1] = ex2_f16x2(pack_f16(cs0[3], cs0[2]));  // rows g+8
            a[2] = ex2_f16x2(pack_f16(cs1[1], cs1[0]));  // rows g,   cols +8
            a[3] = ex2_f16x2(pack_f16(cs1[3], cs1[2]));  // rows g+8

            sg2  = hadd2(sg2,  hadd2(a[0], a[2]));
            sg82 = hadd2(sg82, hadd2(a[1], a[3]));

            mma_f16a(o[0], a, vbuf[g * VS2_STRIDE + kb * 8 + q],
                              vbuf[g * VS2_STRIDE + kb * 8 + q + 4]);
            mma_f16a(o[1], a, vbuf[(8 + g) * VS2_STRIDE + kb * 8 + q],
                              vbuf[(8 + g) * VS2_STRIDE + kb * 8 + q + 4]);
        }

        // fold this kt's f16x2 partial sums into fp32
        float2 f0 = __half22float2(*reinterpret_cast<__half2*>(&sg2));
        float2 f1 = __half22float2(*reinterpret_cast<__half2*>(&sg82));
        sum_g  += f0.x + f0.y;
        sum_g8 += f1.x + f1.y;
    }

    sum_g  += __shfl_xor_sync(0xffffffffu, sum_g, 1);
    sum_g  += __shfl_xor_sync(0xffffffffu, sum_g, 2);
    sum_g8 += __shfl_xor_sync(0xffffffffu, sum_g8, 1);
    sum_g8 += __shfl_xor_sync(0xffffffffu, sum_g8, 2);
    const float il_g = 1.f / sum_g, il_g8 = 1.f / sum_g8;

    const size_t nb = (size_t)(b * 8 + h) * N_SP;
    #pragma unroll
    for (int nt = 0; nt < 2; nt++) {
        float* d0 = g_attn + (nb + qbase + g)     * 16 + nt * 8 + 2 * q;
        float* d8 = g_attn + (nb + qbase + g + 8) * 16 + nt * 8 + 2 * q;
        *(float2*)d0 = make_float2(o[nt][0] * il_g,  o[nt][1] * il_g);
        *(float2*)d8 = make_float2(o[nt][2] * il_g8, o[nt][3] * il_g8);
    }
}

// ---------------------------------------------------------------------------
// Kernel 3: 1x1 projection, tf32 mma: C[128oc,64n] = W[128,128]*A[128,64n]
// ---------------------------------------------------------------------------
#define PW_STRIDE 132
#define PA_STRIDE 72

__global__ __launch_bounds__(256) void proj_mma_kernel(
    const float* __restrict__ w_out, float* __restrict__ out)
{
    extern __shared__ float smf[];
    float* w_s = smf;                   // [128][132]
    float* a_s = smf + 128 * PW_STRIDE; // [128][72]

    const int b  = blockIdx.y;
    const int n0 = blockIdx.x * 64;
    const int tid = threadIdx.x, wid = tid >> 5, lane = tid & 31;
    const int g = lane >> 2, q = lane & 3;

    const float4* wsrc = (const float4*)w_out;
    #pragma unroll
    for (int i = 0; i < 16; i++) {
        int e4 = tid + i * 256;
        int oc = e4 >> 5, ic4 = e4 & 31;
        *(float4*)&w_s[oc * PW_STRIDE + ic4 * 4] = wsrc[e4];
    }
    #pragma unroll
    for (int i = 0; i < 8; i++) {
        int e4 = tid + i * 256;
        int ic = e4 >> 4, c4 = e4 & 15;
        *(float4*)&a_s[ic * PA_STRIDE + c4 * 4] =
            *(const float4*)&g_attn[(size_t)(b * 128 + ic) * N_SP + n0 + c4 * 4];
    }
    __syncthreads();

    const uint32_t* ws = (const uint32_t*)w_s;
    const uint32_t* as = (const uint32_t*)a_s;

    float c[8][4];
    #pragma unroll
    for (int j = 0; j < 8; j++)
        #pragma unroll
        for (int t = 0; t < 4; t++) c[j][t] = 0.f;

    #pragma unroll
    for (int ks = 0; ks < 16; ks++) {
        uint32_t a[4];
        int r0 = (wid * 16 + g) * PW_STRIDE + ks * 8 + q;
        a[0] = ws[r0];
        a[1] = ws[r0 + 8 * PW_STRIDE];
        a[2] = ws[r0 + 4];
        a[3] = ws[r0 + 8 * PW_STRIDE + 4];
        #pragma unroll
        for (int j = 0; j < 8; j++) {
            uint32_t b0 = as[(ks * 8 + q)     * PA_STRIDE + j * 8 + g];
            uint32_t b1 = as[(ks * 8 + q + 4) * PA_STRIDE + j * 8 + g];
            mma_tf32(c[j], a, b0, b1);
        }
    }

    #pragma unroll
    for (int j = 0; j < 8; j++) {
        int oc  = wid * 16 + g;
        int col = n0 + j * 8 + 2 * q;
        float* p = out + (size_t)(b * 256 + 128 + oc) * N_SP;
        *(float2*)&p[col]            = make_float2(c[j][0], c[j][1]);
        *(float2*)&p[8 * N_SP + col] = make_float2(c[j][2], c[j][3]);
    }
}

// ---------------------------------------------------------------------------
extern "C" void kernel_launch(void* const* d_in, const int* in_sizes, int n_in,
                              void* d_out, int out_size)
{
    const float* x      = (const float*)d_in[0];
    const float* w_init = (const float*)d_in[1];
    const float* w_qkv  = (const float*)d_in[2];
    const float* w_out  = (const float*)d_in[3];
    float* out = (float*)d_out;

    const int conv_smem = (XS_U32 + 2 * WCHUNK) * 4;               // 90112 B
    const int attn_smem = (2 * KBUF) * 4 + (2 * VBUF) * 4;         // 26112 B
    const int proj_smem = (128 * PW_STRIDE + 128 * PA_STRIDE) * 4; // 104448 B
    cudaFuncSetAttribute(conv_mma_kernel,
                         cudaFuncAttributeMaxDynamicSharedMemorySize, conv_smem);
    cudaFuncSetAttribute(attn_mma_kernel,
                         cudaFuncAttributeMaxDynamicSharedMemorySize, attn_smem);
    cudaFuncSetAttribute(proj_mma_kernel,
                         cudaFuncAttributeMaxDynamicSharedMemorySize, proj_smem);

    wprep_kernel<<<288, 1024>>>(w_init, w_qkv);

    dim3 cg(4, 24, 4);
    conv_mma_kernel<<<cg, 256, conv_smem>>>(x, out);

    dim3 ag(18, 8, 4);
    attn_mma_kernel<<<ag, 256, attn_smem>>>();

    dim3 pg(36, 4);
    proj_mma_kernel<<<pg, 256, proj_smem>>>(w_out, out);
}

// round 13
// speedup vs baseline: 1.3144x; 1.0784x over previous
#include <cuda_runtime.h>
#include <cuda_bf16.h>
#include <cuda_fp16.h>
#include <cstdint>

// Scratch (allocation-free rule: __device__ globals)
__device__ float    g_qkv[4 * 384 * 2304];  // (b,384,N): q=0..127, k=128..255
__device__ uint32_t g_vbf[4 * 128 * 1152];  // V packed f16x2 key-pairs: [b][vch][keypair]
__device__ float    g_attn[4 * 128 * 2304]; // (b,8,N,16) contiguous == (b,128,N) reinterpret
__device__ uint32_t g_w[9 * 2 * 4 * 4096];  // conv weights fp16x2: [tap][half][ocg][4096]

#define N_SP 2304   // 48*48

__device__ __forceinline__ uint32_t to_tf32(float f) {
    uint32_t t;
    asm("cvt.rna.tf32.f32 %0, %1;" : "=r"(t) : "f"(f));
    return t;
}

__device__ __forceinline__ uint32_t pack_f16(float hi, float lo) {
    uint32_t r;
    asm("cvt.rn.f16x2.f32 %0, %1, %2;" : "=r"(r) : "f"(hi), "f"(lo));
    return r;
}

__device__ __forceinline__ uint32_t ex2_f16x2(uint32_t v) {
    uint32_t r;
    asm("ex2.approx.f16x2 %0, %1;" : "=r"(r) : "r"(v));
    return r;
}

__device__ __forceinline__ uint32_t hadd2(uint32_t a, uint32_t b) {
    uint32_t r;
    asm("add.rn.f16x2 %0, %1, %2;" : "=r"(r) : "r"(a), "r"(b));
    return r;
}

__device__ __forceinline__ void mma_tf32(float c[4], const uint32_t a[4],
                                         uint32_t b0, uint32_t b1)
{
    asm volatile(
        "mma.sync.aligned.m16n8k8.row.col.f32.tf32.tf32.f32 "
        "{%0,%1,%2,%3}, {%4,%5,%6,%7}, {%8,%9}, {%0,%1,%2,%3};"
        : "+f"(c[0]), "+f"(c[1]), "+f"(c[2]), "+f"(c[3])
        : "r"(a[0]), "r"(a[1]), "r"(a[2]), "r"(a[3]), "r"(b0), "r"(b1));
}

__device__ __forceinline__ void mma_f16v(float c[4], uint4 a,
                                         uint32_t b0, uint32_t b1)
{
    asm volatile(
        "mma.sync.aligned.m16n8k16.row.col.f32.f16.f16.f32 "
        "{%0,%1,%2,%3}, {%4,%5,%6,%7}, {%8,%9}, {%0,%1,%2,%3};"
        : "+f"(c[0]), "+f"(c[1]), "+f"(c[2]), "+f"(c[3])
        : "r"(a.x), "r"(a.y), "r"(a.z), "r"(a.w), "r"(b0), "r"(b1));
}

__device__ __forceinline__ void mma_f16a(float c[4], const uint32_t a[4],
                                         uint32_t b0, uint32_t b1)
{
    asm volatile(
        "mma.sync.aligned.m16n8k16.row.col.f32.f16.f16.f32 "
        "{%0,%1,%2,%3}, {%4,%5,%6,%7}, {%8,%9}, {%0,%1,%2,%3};"
        : "+f"(c[0]), "+f"(c[1]), "+f"(c[2]), "+f"(c[3])
        : "r"(a[0]), "r"(a[1]), "r"(a[2]), "r"(a[3]), "r"(b0), "r"(b1));
}

__device__ __forceinline__ void cp_async16(uint32_t smem_addr, const void* gptr) {
    asm volatile("cp.async.cg.shared.global [%0], [%1], 16;"
                 :: "r"(smem_addr), "l"(gptr));
}
#define CP_COMMIT() asm volatile("cp.async.commit_group;" ::: "memory")
#define CP_WAIT0()  asm volatile("cp.async.wait_group 0;" ::: "memory")

// ---------------------------------------------------------------------------
// Kernel 0: pack conv weights as fp16x2 ic-pairs in m16n8k16 A-frag order.
// Chunk (16KB = 4096 u32) = (tap, half, ocg): [ob 8][icclo 4][lane 32][e 4]
// ---------------------------------------------------------------------------
__global__ __launch_bounds__(1024) void wprep_kernel(
    const float* __restrict__ w_init, const float* __restrict__ w_qkv)
{
    int idx = blockIdx.x * 1024 + threadIdx.x;   // 294912 total
    int e     = idx & 3;
    int lane  = (idx >> 2) & 31;
    int icclo = (idx >> 7) & 3;
    int ob    = (idx >> 9) & 7;
    int ocg   = (idx >> 12) & 3;
    int half  = (idx >> 14) & 1;
    int tap   = idx >> 15;
    int g = lane >> 2, q = lane & 3;
    int icc = half * 4 + icclo;
    int oc = ocg * 128 + ob * 16 + g + (e & 1) * 8;
    int ic = icc * 16 + 2 * q + ((e >> 1) & 1) * 8;
    float w0, w1;
    if (oc < 128) {
        w0 = w_init[(oc * 128 + ic) * 9 + tap];
        w1 = w_init[(oc * 128 + ic + 1) * 9 + tap];
    } else {
        w0 = w_qkv[((oc - 128) * 128 + ic) * 9 + tap];
        w1 = w_qkv[((oc - 128) * 128 + ic + 1) * 9 + tap];
    }
    g_w[idx] = pack_f16(w1, w0);
}

// ---------------------------------------------------------------------------
// Kernel 1: 3x3 circular conv, fp16 mma implicit GEMM.
// X staged via warp-per-line COALESCED loads (lanes sweep columns).
// 2 CTAs/SM (90KB). CTA = 128 oc x 96 pos (2 rows), 8 warps = 4(M) x 2(row).
// ---------------------------------------------------------------------------
#define XS_STRIDE 56                      // u32 per (row, icpair) line
#define XS_U32 (4 * 64 * XS_STRIDE)       // 14336 u32 = 57344 B
#define WCHUNK 4096                       // u32 per weight chunk (16 KB)

__global__ __launch_bounds__(256, 2) void conv_mma_kernel(
    const float* __restrict__ x, float* __restrict__ out)
{
    extern __shared__ uint32_t smu[];
    uint32_t* x_s = smu;                  // [4 rows][64 icpair][56]
    uint32_t* w_s = smu + XS_U32;         // [2][4096]

    const int b   = blockIdx.z;
    const int rp  = blockIdx.y;
    const int ocg = blockIdx.x;
    const int tid = threadIdx.x;
    const int wid = tid >> 5, lane = tid & 31;
    const int warp_m = wid & 3;
    const int warp_n = wid >> 2;
    const int g = lane >> 2, q = lane & 3;

    const uint32_t ws_u32 = (uint32_t)__cvta_generic_to_shared(w_s);

    // chunk c (0..17): tap = c>>1, half = c&1
    auto stage_w = [&](int c) {
        const float4* src = (const float4*)(g_w + ((size_t)c * 4 + ocg) * WCHUNK);
        uint32_t dst = ws_u32 + (uint32_t)(c & 1) * (WCHUNK * 4);
        #pragma unroll
        for (int i = 0; i < 4; i++) {
            int e4 = tid + i * 256;       // 1024 float4
            cp_async16(dst + e4 * 16, src + e4);
        }
    };

    stage_w(0); CP_COMMIT();

    // stage x: warp per (row, icpair) line; lanes sweep columns (coalesced).
    #pragma unroll
    for (int li = 0; li < 32; li++) {
        int l = wid + li * 8;             // 256 lines
        int r = l >> 6, icp = l & 63;
        int srow = (2 * rp - 1 + r + 48) % 48;
        const float* s0 = x + ((b * 128 + 2 * icp) * 48 + srow) * 48;
        const float* s1 = s0 + 2304;      // next ic row
        uint32_t* dst = &x_s[(r * 64 + icp) * XS_STRIDE];
        dst[2 + lane] = pack_f16(s1[lane], s0[lane]);          // cols 0..31
        if (lane < 16)
            dst[34 + lane] = pack_f16(s1[32 + lane], s0[32 + lane]); // 32..47
        else if (lane == 16)
            dst[1]  = pack_f16(s1[47], s0[47]);                // wrap left
        else if (lane == 17)
            dst[50] = pack_f16(s1[0], s0[0]);                  // wrap right
    }

    float c_acc[2][6][4];
    #pragma unroll
    for (int mi = 0; mi < 2; mi++)
        #pragma unroll
        for (int j = 0; j < 6; j++)
            #pragma unroll
            for (int t = 0; t < 4; t++) c_acc[mi][j][t] = 0.f;

    for (int c = 0; c < 18; c++) {
        CP_WAIT0();
        __syncthreads();
        if (c < 17) { stage_w(c + 1); CP_COMMIT(); }

        const int tap = c >> 1, half = c & 1;
        const int dr = tap / 3 - 1, dc = tap % 3 - 1;
        const int irow = warp_n + dr + 1;
        const int colb = dc + 2 + g;
        const uint32_t* xrow = x_s + irow * 64 * XS_STRIDE;
        const uint4* wbuf = (const uint4*)(w_s + (c & 1) * WCHUNK);

        #pragma unroll
        for (int icclo = 0; icclo < 4; icclo++) {
            const int icc = half * 4 + icclo;
            uint4 a0 = wbuf[((warp_m * 2 + 0) * 4 + icclo) * 32 + lane];
            uint4 a1 = wbuf[((warp_m * 2 + 1) * 4 + icclo) * 32 + lane];
            #pragma unroll
            for (int j = 0; j < 6; j++) {
                uint32_t b0 = xrow[(icc * 8 + q)     * XS_STRIDE + colb + j * 8];
                uint32_t b1 = xrow[(icc * 8 + q + 4) * XS_STRIDE + colb + j * 8];
                mma_f16v(c_acc[0][j], a0, b0, b1);
                mma_f16v(c_acc[1][j], a1, b0, b1);
            }
        }
    }

    const int orow = 2 * rp + warp_n;
    const int spat = orow * 48;
    #pragma unroll
    for (int mi = 0; mi < 2; mi++) {
        int oc_l = ocg * 128 + warp_m * 32 + mi * 16 + g;
        if (oc_l < 384) {
            float* p = (oc_l < 128)
                ? out   + (size_t)(b * 256 + oc_l) * N_SP
                : g_qkv + (size_t)(b * 384 + oc_l - 128) * N_SP;
            float* p8 = p + 8 * N_SP;
            #pragma unroll
            for (int j = 0; j < 6; j++) {
                int col = j * 8 + 2 * q;
                *(float2*)&p [spat + col] = make_float2(c_acc[mi][j][0], c_acc[mi][j][1]);
                *(float2*)&p8[spat + col] = make_float2(c_acc[mi][j][2], c_acc[mi][j][3]);
            }
        } else {
            int vch = oc_l - 384;
            uint32_t* v0 = g_vbf + (size_t)(b * 128 + vch) * 1152 + orow * 24;
            uint32_t* v8 = v0 + 8 * 1152;
            #pragma unroll
            for (int j = 0; j < 6; j++) {
                v0[j * 4 + q] = pack_f16(c_acc[mi][j][1], c_acc[mi][j][0]);
                v8[j * 4 + q] = pack_f16(c_acc[mi][j][3], c_acc[mi][j][2]);
            }
        }
    }
}

// ---------------------------------------------------------------------------
// Kernel 2: flash attention. S: tf32 mma. Softmax: ex2.approx.f16x2 feeding
// f16 PV mma directly. No-max softmax. (R12 configuration, unchanged.)
// ---------------------------------------------------------------------------
#define KS_STRIDE 136    // K smem: [ch][key] fp32
#define VS2_STRIDE 68    // V smem: [dv][keypair] u32 f16x2
#define KBUF (16 * KS_STRIDE)
#define VBUF (16 * VS2_STRIDE)

__global__ __launch_bounds__(256, 2) void attn_mma_kernel()
{
    extern __shared__ float sm[];
    float*    k_s = sm;                          // [2][16][136]
    uint32_t* v_s = (uint32_t*)(sm + 2 * KBUF);  // [2][16][68]

    const int b = blockIdx.z, h = blockIdx.y, qt = blockIdx.x;
    const int tid = threadIdx.x, wid = tid >> 5, lane = tid & 31;
    const int g = lane >> 2, q = lane & 3;
    const int qbase = qt * 128 + wid * 16;

    const float*    qptr = g_qkv + (size_t)(b * 384 + h * 16) * N_SP;
    const float*    kptr = g_qkv + (size_t)(b * 384 + 128 + h * 16) * N_SP;
    const uint32_t* vptr = g_vbf + (size_t)(b * 128 + h * 16) * 1152;

    const uint32_t ks_u32 = (uint32_t)__cvta_generic_to_shared(k_s);
    const uint32_t vs_u32 = (uint32_t)__cvta_generic_to_shared(v_s);

    auto stage = [&](int kt) {
        uint32_t buf = (uint32_t)(kt & 1);
        #pragma unroll
        for (int it = 0; it < 2; it++) {
            int i  = tid + it * 256;
            int ch = i >> 5, k4 = i & 31;
            cp_async16(ks_u32 + (buf * KBUF + ch * KS_STRIDE + k4 * 4) * 4,
                       kptr + ch * N_SP + kt * 128 + k4 * 4);
        }
        {
            int ch = tid >> 4, kp4 = tid & 15;
            cp_async16(vs_u32 + (buf * VBUF + ch * VS2_STRIDE + kp4 * 4) * 4,
                       vptr + ch * 1152 + kt * 64 + kp4 * 4);
        }
    };

    stage(0); CP_COMMIT();

    const float qscale = 0.25f * 1.4426950408889634f;  // dk^-0.5 * log2(e)
    uint32_t qa[2][4];
    #pragma unroll
    for (int s = 0; s < 2; s++) {
        qa[s][0] = to_tf32(qptr[(s * 8 + q)     * N_SP + qbase + g]     * qscale);
        qa[s][1] = to_tf32(qptr[(s * 8 + q)     * N_SP + qbase + g + 8] * qscale);
        qa[s][2] = to_tf32(qptr[(s * 8 + q + 4) * N_SP + qbase + g]     * qscale);
        qa[s][3] = to_tf32(qptr[(s * 8 + q + 4) * N_SP + qbase + g + 8] * qscale);
    }

    float sum_g = 0.f, sum_g8 = 0.f;
    float o[2][4];
    #pragma unroll
    for (int nt = 0; nt < 2; nt++)
        #pragma unroll
        for (int t = 0; t < 4; t++) o[nt][t] = 0.f;

    for (int kt = 0; kt < 18; kt++) {
        CP_WAIT0();
        __syncthreads();
        if (kt < 17) { stage(kt + 1); CP_COMMIT(); }

        const uint32_t* ks32 = (const uint32_t*)(k_s + (kt & 1) * KBUF);
        const uint32_t* vbuf = v_s + (kt & 1) * VBUF;

        uint32_t sg2 = 0, sg82 = 0;             // f16x2 partial sums (this kt)

        #pragma unroll
        for (int kb = 0; kb < 8; kb++) {        // 16 keys per block
            float cs0[4] = {0.f, 0.f, 0.f, 0.f};
            float cs1[4] = {0.f, 0.f, 0.f, 0.f};
            #pragma unroll
            for (int s = 0; s < 2; s++) {
                int r0 = (s * 8 + q) * KS_STRIDE + kb * 16 + g;
                int r1 = (s * 8 + q + 4) * KS_STRIDE + kb * 16 + g;
                mma_tf32(cs0, qa[s], ks32[r0],     ks32[r1]);
                mma_tf32(cs1, qa[s], ks32[r0 + 8], ks32[r1 + 8]);
            }

            // pack logit pairs -> 2-exps-per-MUFU -> f16 PV A-fragment
            uint32_t a[4];
            a[0] = ex2_f16x2(pack_f16(cs0[1], cs0[0]));  // rows g,   cols 2q,2q+1
            a[1] = ex2_f16x2(pack_f16(cs0[3], cs0[2]));  // rows g+8
            a[2] = ex2_f16x2(pack_f16(cs1[1], cs1[0]));  // rows g,   cols +8
            a[3] = ex2_f16x2(pack_f16(cs1[3], cs1[2]));  // rows g+8

            sg2  = hadd2(sg2,  hadd2(a[0], a[2]));
            sg82 = hadd2(sg82, hadd2(a[1], a[3]));

            mma_f16a(o[0], a, vbuf[g * VS2_STRIDE + kb * 8 + q],
                              vbuf[g * VS2_STRIDE + kb * 8 + q + 4]);
            mma_f16a(o[1], a, vbuf[(8 + g) * VS2_STRIDE + kb * 8 + q],
                              vbuf[(8 + g) * VS2_STRIDE + kb * 8 + q + 4]);
        }

        // fold this kt's f16x2 partial sums into fp32
        float2 f0 = __half22float2(*reinterpret_cast<__half2*>(&sg2));
        float2 f1 = __half22float2(*reinterpret_cast<__half2*>(&sg82));
        sum_g  += f0.x + f0.y;
        sum_g8 += f1.x + f1.y;
    }

    sum_g  += __shfl_xor_sync(0xffffffffu, sum_g, 1);
    sum_g  += __shfl_xor_sync(0xffffffffu, sum_g, 2);
    sum_g8 += __shfl_xor_sync(0xffffffffu, sum_g8, 1);
    sum_g8 += __shfl_xor_sync(0xffffffffu, sum_g8, 2);
    const float il_g = 1.f / sum_g, il_g8 = 1.f / sum_g8;

    const size_t nb = (size_t)(b * 8 + h) * N_SP;
    #pragma unroll
    for (int nt = 0; nt < 2; nt++) {
        float* d0 = g_attn + (nb + qbase + g)     * 16 + nt * 8 + 2 * q;
        float* d8 = g_attn + (nb + qbase + g + 8) * 16 + nt * 8 + 2 * q;
        *(float2*)d0 = make_float2(o[nt][0] * il_g,  o[nt][1] * il_g);
        *(float2*)d8 = make_float2(o[nt][2] * il_g8, o[nt][3] * il_g8);
    }
}

// ---------------------------------------------------------------------------
// Kernel 3: 1x1 projection, tf32 mma: C[128oc,64n] = W[128,128]*A[128,64n]
// ---------------------------------------------------------------------------
#define PW_STRIDE 132
#define PA_STRIDE 72

__global__ __launch_bounds__(256) void proj_mma_kernel(
    const float* __restrict__ w_out, float* __restrict__ out)
{
    extern __shared__ float smf[];
    float* w_s = smf;                   // [128][132]
    float* a_s = smf + 128 * PW_STRIDE; // [128][72]

    const int b  = blockIdx.y;
    const int n0 = blockIdx.x * 64;
    const int tid = threadIdx.x, wid = tid >> 5, lane = tid & 31;
    const int g = lane >> 2, q = lane & 3;

    const float4* wsrc = (const float4*)w_out;
    #pragma unroll
    for (int i = 0; i < 16; i++) {
        int e4 = tid + i * 256;
        int oc = e4 >> 5, ic4 = e4 & 31;
        *(float4*)&w_s[oc * PW_STRIDE + ic4 * 4] = wsrc[e4];
    }
    #pragma unroll
    for (int i = 0; i < 8; i++) {
        int e4 = tid + i * 256;
        int ic = e4 >> 4, c4 = e4 & 15;
        *(float4*)&a_s[ic * PA_STRIDE + c4 * 4] =
            *(const float4*)&g_attn[(size_t)(b * 128 + ic) * N_SP + n0 + c4 * 4];
    }
    __syncthreads();

    const uint32_t* ws = (const uint32_t*)w_s;
    const uint32_t* as = (const uint32_t*)a_s;

    float c[8][4];
    #pragma unroll
    for (int j = 0; j < 8; j++)
        #pragma unroll
        for (int t = 0; t < 4; t++) c[j][t] = 0.f;

    #pragma unroll
    for (int ks = 0; ks < 16; ks++) {
        uint32_t a[4];
        int r0 = (wid * 16 + g) * PW_STRIDE + ks * 8 + q;
        a[0] = ws[r0];
        a[1] = ws[r0 + 8 * PW_STRIDE];
        a[2] = ws[r0 + 4];
        a[3] = ws[r0 + 8 * PW_STRIDE + 4];
        #pragma unroll
        for (int j = 0; j < 8; j++) {
            uint32_t b0 = as[(ks * 8 + q)     * PA_STRIDE + j * 8 + g];
            uint32_t b1 = as[(ks * 8 + q + 4) * PA_STRIDE + j * 8 + g];
            mma_tf32(c[j], a, b0, b1);
        }
    }

    #pragma unroll
    for (int j = 0; j < 8; j++) {
        int oc  = wid * 16 + g;
        int col = n0 + j * 8 + 2 * q;
        float* p = out + (size_t)(b * 256 + 128 + oc) * N_SP;
        *(float2*)&p[col]            = make_float2(c[j][0], c[j][1]);
        *(float2*)&p[8 * N_SP + col] = make_float2(c[j][2], c[j][3]);
    }
}

// ---------------------------------------------------------------------------
extern "C" void kernel_launch(void* const* d_in, const int* in_sizes, int n_in,
                              void* d_out, int out_size)
{
    const float* x      = (const float*)d_in[0];
    const float* w_init = (const float*)d_in[1];
    const float* w_qkv  = (const float*)d_in[2];
    const float* w_out  = (const float*)d_in[3];
    float* out = (float*)d_out;

    const int conv_smem = (XS_U32 + 2 * WCHUNK) * 4;               // 90112 B
    const int attn_smem = (2 * KBUF) * 4 + (2 * VBUF) * 4;         // 26112 B
    const int proj_smem = (128 * PW_STRIDE + 128 * PA_STRIDE) * 4; // 104448 B
    cudaFuncSetAttribute(conv_mma_kernel,
                         cudaFuncAttributeMaxDynamicSharedMemorySize, conv_smem);
    cudaFuncSetAttribute(attn_mma_kernel,
                         cudaFuncAttributeMaxDynamicSharedMemorySize, attn_smem);
    cudaFuncSetAttribute(proj_mma_kernel,
                         cudaFuncAttributeMaxDynamicSharedMemorySize, proj_smem);

    wprep_kernel<<<288, 1024>>>(w_init, w_qkv);

    dim3 cg(4, 24, 4);
    conv_mma_kernel<<<cg, 256, conv_smem>>>(x, out);

    dim3 ag(18, 8, 4);
    attn_mma_kernel<<<ag, 256, attn_smem>>>();

    dim3 pg(36, 4);
    proj_mma_kernel<<<pg, 256, proj_smem>>>(w_out, out);
}

// round 15
// speedup vs baseline: 1.4368x; 1.0931x over previous
#include <cuda_runtime.h>
#include <cuda_bf16.h>
#include <cuda_fp16.h>
#include <cstdint>

// Scratch (allocation-free rule: __device__ globals)
__device__ float    g_qkv[4 * 384 * 2304];  // (b,384,N): q=0..127, k=128..255
__device__ uint32_t g_vbf[4 * 128 * 1152];  // V packed f16x2 key-pairs: [b][vch][keypair]
__device__ float    g_attn[4 * 128 * 2304]; // (b,8,N,16) contiguous == (b,128,N) reinterpret
__device__ uint32_t g_w[9 * 2 * 4 * 4096];  // conv weights fp16x2: [tap][half][ocg][4096]

#define N_SP 2304   // 48*48

__device__ __forceinline__ uint32_t to_tf32(float f) {
    uint32_t t;
    asm("cvt.rna.tf32.f32 %0, %1;" : "=r"(t) : "f"(f));
    return t;
}

__device__ __forceinline__ uint32_t pack_f16(float hi, float lo) {
    uint32_t r;
    asm("cvt.rn.f16x2.f32 %0, %1, %2;" : "=r"(r) : "f"(hi), "f"(lo));
    return r;
}

__device__ __forceinline__ uint32_t ex2_f16x2(uint32_t v) {
    uint32_t r;
    asm("ex2.approx.f16x2 %0, %1;" : "=r"(r) : "r"(v));
    return r;
}

__device__ __forceinline__ uint32_t hadd2(uint32_t a, uint32_t b) {
    uint32_t r;
    asm("add.rn.f16x2 %0, %1, %2;" : "=r"(r) : "r"(a), "r"(b));
    return r;
}

__device__ __forceinline__ void mma_tf32(float c[4], const uint32_t a[4],
                                         uint32_t b0, uint32_t b1)
{
    asm volatile(
        "mma.sync.aligned.m16n8k8.row.col.f32.tf32.tf32.f32 "
        "{%0,%1,%2,%3}, {%4,%5,%6,%7}, {%8,%9}, {%0,%1,%2,%3};"
        : "+f"(c[0]), "+f"(c[1]), "+f"(c[2]), "+f"(c[3])
        : "r"(a[0]), "r"(a[1]), "r"(a[2]), "r"(a[3]), "r"(b0), "r"(b1));
}

__device__ __forceinline__ void mma_f16v(float c[4], uint4 a,
                                         uint32_t b0, uint32_t b1)
{
    asm volatile(
        "mma.sync.aligned.m16n8k16.row.col.f32.f16.f16.f32 "
        "{%0,%1,%2,%3}, {%4,%5,%6,%7}, {%8,%9}, {%0,%1,%2,%3};"
        : "+f"(c[0]), "+f"(c[1]), "+f"(c[2]), "+f"(c[3])
        : "r"(a.x), "r"(a.y), "r"(a.z), "r"(a.w), "r"(b0), "r"(b1));
}

__device__ __forceinline__ void mma_f16a(float c[4], const uint32_t a[4],
                                         uint32_t b0, uint32_t b1)
{
    asm volatile(
        "mma.sync.aligned.m16n8k16.row.col.f32.f16.f16.f32 "
        "{%0,%1,%2,%3}, {%4,%5,%6,%7}, {%8,%9}, {%0,%1,%2,%3};"
        : "+f"(c[0]), "+f"(c[1]), "+f"(c[2]), "+f"(c[3])
        : "r"(a[0]), "r"(a[1]), "r"(a[2]), "r"(a[3]), "r"(b0), "r"(b1));
}

__device__ __forceinline__ void cp_async16(uint32_t smem_addr, const void* gptr) {
    asm volatile("cp.async.cg.shared.global [%0], [%1], 16;"
                 :: "r"(smem_addr), "l"(gptr));
}
#define CP_COMMIT() asm volatile("cp.async.commit_group;" ::: "memory")
#define CP_WAIT0()  asm volatile("cp.async.wait_group 0;" ::: "memory")

// ---------------------------------------------------------------------------
// Kernel 0: pack conv weights as fp16x2 ic-pairs in m16n8k16 A-frag order.
// Chunk (16KB = 4096 u32) = (tap, half, ocg): [ob 8][icclo 4][lane 32][e 4]
// ---------------------------------------------------------------------------
__global__ __launch_bounds__(1024) void wprep_kernel(
    const float* __restrict__ w_init, const float* __restrict__ w_qkv)
{
    int idx = blockIdx.x * 1024 + threadIdx.x;   // 294912 total
    int e     = idx & 3;
    int lane  = (idx >> 2) & 31;
    int icclo = (idx >> 7) & 3;
    int ob    = (idx >> 9) & 7;
    int ocg   = (idx >> 12) & 3;
    int half  = (idx >> 14) & 1;
    int tap   = idx >> 15;
    int g = lane >> 2, q = lane & 3;
    int icc = half * 4 + icclo;
    int oc = ocg * 128 + ob * 16 + g + (e & 1) * 8;
    int ic = icc * 16 + 2 * q + ((e >> 1) & 1) * 8;
    float w0, w1;
    if (oc < 128) {
        w0 = w_init[(oc * 128 + ic) * 9 + tap];
        w1 = w_init[(oc * 128 + ic + 1) * 9 + tap];
    } else {
        w0 = w_qkv[((oc - 128) * 128 + ic) * 9 + tap];
        w1 = w_qkv[((oc - 128) * 128 + ic + 1) * 9 + tap];
    }
    g_w[idx] = pack_f16(w1, w0);
}

// ---------------------------------------------------------------------------
// Kernel 1: 3x3 circular conv, fp16 mma implicit GEMM.
// THREE output rows per CTA -> grid 256 CTAs = one full wave at 2 CTAs/SM.
// CTA = 128 oc x 144 pos; 8 warps = 4(oc) x 2(pos-half of 72 = 9 j-tiles).
// x-tile: 5 halo rows (70KB) + 2x16KB weight buffers = 102KB smem.
// ---------------------------------------------------------------------------
#define XS_STRIDE 56                      // u32 per (row, icpair) line
#define XS_U32 (5 * 64 * XS_STRIDE)       // 17920 u32 = 71680 B
#define WCHUNK 4096                       // u32 per weight chunk (16 KB)

__global__ __launch_bounds__(256, 2) void conv_mma_kernel(
    const float* __restrict__ x, float* __restrict__ out)
{
    extern __shared__ uint32_t smu[];
    uint32_t* x_s = smu;                  // [5 rows][64 icpair][56]
    uint32_t* w_s = smu + XS_U32;         // [2][4096]

    const int b   = blockIdx.z;
    const int rp  = blockIdx.y;           // row triple: rows 3rp..3rp+2
    const int ocg = blockIdx.x;
    const int tid = threadIdx.x;
    const int wid = tid >> 5, lane = tid & 31;
    const int warp_m = wid & 3;
    const int warp_n = wid >> 2;          // position half (72 pos each)
    const int g = lane >> 2, q = lane & 3;

    // per-warp j-tile geometry: flattened pos = warp_n*72 + jj*8
    int rowj[9], colj[9];
    #pragma unroll
    for (int jj = 0; jj < 9; jj++) {
        int flat = warp_n * 72 + jj * 8;
        rowj[jj] = flat / 48;
        colj[jj] = flat - rowj[jj] * 48;
    }

    const uint32_t ws_u32 = (uint32_t)__cvta_generic_to_shared(w_s);

    // chunk c (0..17): tap = c>>1, half = c&1
    auto stage_w = [&](int c) {
        const float4* src = (const float4*)(g_w + ((size_t)c * 4 + ocg) * WCHUNK);
        uint32_t dst = ws_u32 + (uint32_t)(c & 1) * (WCHUNK * 4);
        #pragma unroll
        for (int i = 0; i < 4; i++) {
            int e4 = tid + i * 256;       // 1024 float4
            cp_async16(dst + e4 * 16, src + e4);
        }
    };

    stage_w(0); CP_COMMIT();

    // stage x: warp per (row, icpair) line; lanes sweep columns (coalesced).
    #pragma unroll
    for (int li = 0; li < 40; li++) {
        int l = wid + li * 8;             // 320 lines (5 rows x 64 icp)
        int r = l >> 6, icp = l & 63;
        int srow = (3 * rp - 1 + r + 48) % 48;
        const float* s0 = x + ((b * 128 + 2 * icp) * 48 + srow) * 48;
        const float* s1 = s0 + 2304;      // next ic row
        uint32_t* dst = &x_s[(r * 64 + icp) * XS_STRIDE];
        dst[2 + lane] = pack_f16(s1[lane], s0[lane]);          // cols 0..31
        if (lane < 16)
            dst[34 + lane] = pack_f16(s1[32 + lane], s0[32 + lane]); // 32..47
        else if (lane == 16)
            dst[1]  = pack_f16(s1[47], s0[47]);                // wrap left
        else if (lane == 17)
            dst[50] = pack_f16(s1[0], s0[0]);                  // wrap right
    }

    float c_acc[2][9][4];
    #pragma unroll
    for (int mi = 0; mi < 2; mi++)
        #pragma unroll
        for (int j = 0; j < 9; j++)
            #pragma unroll
            for (int t = 0; t < 4; t++) c_acc[mi][j][t] = 0.f;

    for (int c = 0; c < 18; c++) {
        CP_WAIT0();
        __syncthreads();
        if (c < 17) { stage_w(c + 1); CP_COMMIT(); }

        const int tap = c >> 1, half = c & 1;
        const int dr = tap / 3 - 1, dc = tap % 3 - 1;
        const uint4* wbuf = (const uint4*)(w_s + (c & 1) * WCHUNK);

        #pragma unroll
        for (int icclo = 0; icclo < 4; icclo++) {
            const int icc = half * 4 + icclo;
            uint4 a0 = wbuf[((warp_m * 2 + 0) * 4 + icclo) * 32 + lane];
            uint4 a1 = wbuf[((warp_m * 2 + 1) * 4 + icclo) * 32 + lane];
            #pragma unroll
            for (int jj = 0; jj < 9; jj++) {
                const uint32_t* xrow = x_s + (rowj[jj] + dr + 1) * 64 * XS_STRIDE;
                int cb = colj[jj] + dc + 2 + g;
                uint32_t b0 = xrow[(icc * 8 + q)     * XS_STRIDE + cb];
                uint32_t b1 = xrow[(icc * 8 + q + 4) * XS_STRIDE + cb];
                mma_f16v(c_acc[0][jj], a0, b0, b1);
                mma_f16v(c_acc[1][jj], a1, b0, b1);
            }
        }
    }

    #pragma unroll
    for (int mi = 0; mi < 2; mi++) {
        int oc_l = ocg * 128 + warp_m * 32 + mi * 16 + g;
        if (oc_l < 384) {
            float* p = (oc_l < 128)
                ? out   + (size_t)(b * 256 + oc_l) * N_SP
                : g_qkv + (size_t)(b * 384 + oc_l - 128) * N_SP;
            float* p8 = p + 8 * N_SP;
            #pragma unroll
            for (int jj = 0; jj < 9; jj++) {
                int spat = (3 * rp + rowj[jj]) * 48 + colj[jj] + 2 * q;
                *(float2*)&p [spat] = make_float2(c_acc[mi][jj][0], c_acc[mi][jj][1]);
                *(float2*)&p8[spat] = make_float2(c_acc[mi][jj][2], c_acc[mi][jj][3]);
            }
        } else {
            int vch = oc_l - 384;
            uint32_t* v0 = g_vbf + (size_t)(b * 128 + vch) * 1152;
            uint32_t* v8 = v0 + 8 * 1152;
            #pragma unroll
            for (int jj = 0; jj < 9; jj++) {
                int kp = (3 * rp + rowj[jj]) * 24 + (colj[jj] >> 1) + q;
                v0[kp] = pack_f16(c_acc[0][jj][1], c_acc[0][jj][0]);
                v8[kp] = pack_f16(c_acc[0][jj][3], c_acc[0][jj][2]);
                (void)mi;
            }
            break;  // mi loop handled inside (mi=0 regs used; see note below)
        }
    }
    // NOTE: V path needs both mi tiles; handle mi=1 separately when oc_l>=384.
    {
        int oc_l1 = ocg * 128 + warp_m * 32 + 16 + g;
        if (oc_l1 >= 384) {
            int vch = oc_l1 - 384;
            uint32_t* v0 = g_vbf + (size_t)(b * 128 + vch) * 1152;
            uint32_t* v8 = v0 + 8 * 1152;
            int oc_l0 = oc_l1 - 16;
            if (oc_l0 >= 384) { /* already written above via mi=0 branch */ }
            #pragma unroll
            for (int jj = 0; jj < 9; jj++) {
                int kp = (3 * rp + rowj[jj]) * 24 + (colj[jj] >> 1) + q;
                v0[kp] = pack_f16(c_acc[1][jj][1], c_acc[1][jj][0]);
                v8[kp] = pack_f16(c_acc[1][jj][3], c_acc[1][jj][2]);
            }
        } else if (oc_l1 >= 128 || oc_l1 < 128) {
            // mi=1 non-V path not yet written if the mi loop broke early.
            // The break only happens when mi=0 was already V (>=384), which
            // implies mi=1 is also V (+16 within the same 128-block). For all
            // non-V warps the loop above completed both mi normally.
        }
    }
}

// ---------------------------------------------------------------------------
// Kernel 2: flash attention (frozen R13 config). S: tf32 mma.
// Softmax: ex2.approx.f16x2 feeding f16 PV mma directly. No-max softmax.
// ---------------------------------------------------------------------------
#define KS_STRIDE 136
#define VS2_STRIDE 68
#define KBUF (16 * KS_STRIDE)
#define VBUF (16 * VS2_STRIDE)

__global__ __launch_bounds__(256, 2) void attn_mma_kernel()
{
    extern __shared__ float sm[];
    float*    k_s = sm;                          // [2][16][136]
    uint32_t* v_s = (uint32_t*)(sm + 2 * KBUF);  // [2][16][68]

    const int b = blockIdx.z, h = blockIdx.y, qt = blockIdx.x;
    const int tid = threadIdx.x, wid = tid >> 5, lane = tid & 31;
    const int g = lane >> 2, q = lane & 3;
    const int qbase = qt * 128 + wid * 16;

    const float*    qptr = g_qkv + (size_t)(b * 384 + h * 16) * N_SP;
    const float*    kptr = g_qkv + (size_t)(b * 384 + 128 + h * 16) * N_SP;
    const uint32_t* vptr = g_vbf + (size_t)(b * 128 + h * 16) * 1152;

    const uint32_t ks_u32 = (uint32_t)__cvta_generic_to_shared(k_s);
    const uint32_t vs_u32 = (uint32_t)__cvta_generic_to_shared(v_s);

    auto stage = [&](int kt) {
        uint32_t buf = (uint32_t)(kt & 1);
        #pragma unroll
        for (int it = 0; it < 2; it++) {
            int i  = tid + it * 256;
            int ch = i >> 5, k4 = i & 31;
            cp_async16(ks_u32 + (buf * KBUF + ch * KS_STRIDE + k4 * 4) * 4,
                       kptr + ch * N_SP + kt * 128 + k4 * 4);
        }
        {
            int ch = tid >> 4, kp4 = tid & 15;
            cp_async16(vs_u32 + (buf * VBUF + ch * VS2_STRIDE + kp4 * 4) * 4,
                       vptr + ch * 1152 + kt * 64 + kp4 * 4);
        }
    };

    stage(0); CP_COMMIT();

    const float qscale = 0.25f * 1.4426950408889634f;
    uint32_t qa[2][4];
    #pragma unroll
    for (int s = 0; s < 2; s++) {
        qa[s][0] = to_tf32(qptr[(s * 8 + q)     * N_SP + qbase + g]     * qscale);
        qa[s][1] = to_tf32(qptr[(s * 8 + q)     * N_SP + qbase + g + 8] * qscale);
        qa[s][2] = to_tf32(qptr[(s * 8 + q + 4) * N_SP + qbase + g]     * qscale);
        qa[s][3] = to_tf32(qptr[(s * 8 + q + 4) * N_SP + qbase + g + 8] * qscale);
    }

    float sum_g = 0.f, sum_g8 = 0.f;
    float o[2][4];
    #pragma unroll
    for (int nt = 0; nt < 2; nt++)
        #pragma unroll
        for (int t = 0; t < 4; t++) o[nt][t] = 0.f;

    for (int kt = 0; kt < 18; kt++) {
        CP_WAIT0();
        __syncthreads();
        if (kt < 17) { stage(kt + 1); CP_COMMIT(); }

        const uint32_t* ks32 = (const uint32_t*)(k_s + (kt & 1) * KBUF);
        const uint32_t* vbuf = v_s + (kt & 1) * VBUF;

        uint32_t sg2 = 0, sg82 = 0;

        #pragma unroll
        for (int kb = 0; kb < 8; kb++) {
            float cs0[4] = {0.f, 0.f, 0.f, 0.f};
            float cs1[4] = {0.f, 0.f, 0.f, 0.f};
            #pragma unroll
            for (int s = 0; s < 2; s++) {
                int r0 = (s * 8 + q) * KS_STRIDE + kb * 16 + g;
                int r1 = (s * 8 + q + 4) * KS_STRIDE + kb * 16 + g;
                mma_tf32(cs0, qa[s], ks32[r0],     ks32[r1]);
                mma_tf32(cs1, qa[s], ks32[r0 + 8], ks32[r1 + 8]);
            }

            uint32_t a[4];
            a[0] = ex2_f16x2(pack_f16(cs0[1], cs0[0]));
            a[1] = ex2_f16x2(pack_f16(cs0[3], cs0[2]));
            a[2] = ex2_f16x2(pack_f16(cs1[1], cs1[0]));
            a[3] = ex2_f16x2(pack_f16(cs1[3], cs1[2]));

            sg2  = hadd2(sg2,  hadd2(a[0], a[2]));
            sg82 = hadd2(sg82, hadd2(a[1], a[3]));

            mma_f16a(o[0], a, vbuf[g * VS2_STRIDE + kb * 8 + q],
                              vbuf[g * VS2_STRIDE + kb * 8 + q + 4]);
            mma_f16a(o[1], a, vbuf[(8 + g) * VS2_STRIDE + kb * 8 + q],
                              vbuf[(8 + g) * VS2_STRIDE + kb * 8 + q + 4]);
        }

        float2 f0 = __half22float2(*reinterpret_cast<__half2*>(&sg2));
        float2 f1 = __half22float2(*reinterpret_cast<__half2*>(&sg82));
        sum_g  += f0.x + f0.y;
        sum_g8 += f1.x + f1.y;
    }

    sum_g  += __shfl_xor_sync(0xffffffffu, sum_g, 1);
    sum_g  += __shfl_xor_sync(0xffffffffu, sum_g, 2);
    sum_g8 += __shfl_xor_sync(0xffffffffu, sum_g8, 1);
    sum_g8 += __shfl_xor_sync(0xffffffffu, sum_g8, 2);
    const float il_g = 1.f / sum_g, il_g8 = 1.f / sum_g8;

    const size_t nb = (size_t)(b * 8 + h) * N_SP;
    #pragma unroll
    for (int nt = 0; nt < 2; nt++) {
        float* d0 = g_attn + (nb + qbase + g)     * 16 + nt * 8 + 2 * q;
        float* d8 = g_attn + (nb + qbase + g + 8) * 16 + nt * 8 + 2 * q;
        *(float2*)d0 = make_float2(o[nt][0] * il_g,  o[nt][1] * il_g);
        *(float2*)d8 = make_float2(o[nt][2] * il_g8, o[nt][3] * il_g8);
    }
}

// ---------------------------------------------------------------------------
// Kernel 3: 1x1 projection, tf32 mma (frozen R13 config)
// ---------------------------------------------------------------------------
#define PW_STRIDE 132
#define PA_STRIDE 72

__global__ __launch_bounds__(256) void proj_mma_kernel(
    const float* __restrict__ w_out, float* __restrict__ out)
{
    extern __shared__ float smf[];
    float* w_s = smf;
    float* a_s = smf + 128 * PW_STRIDE;

    const int b  = blockIdx.y;
    const int n0 = blockIdx.x * 64;
    const int tid = threadIdx.x, wid = tid >> 5, lane = tid & 31;
    const int g = lane >> 2, q = lane & 3;

    const float4* wsrc = (const float4*)w_out;
    #pragma unroll
    for (int i = 0; i < 16; i++) {
        int e4 = tid + i * 256;
        int oc = e4 >> 5, ic4 = e4 & 31;
        *(float4*)&w_s[oc * PW_STRIDE + ic4 * 4] = wsrc[e4];
    }
    #pragma unroll
    for (int i = 0; i < 8; i++) {
        int e4 = tid + i * 256;
        int ic = e4 >> 4, c4 = e4 & 15;
        *(float4*)&a_s[ic * PA_STRIDE + c4 * 4] =
            *(const float4*)&g_attn[(size_t)(b * 128 + ic) * N_SP + n0 + c4 * 4];
    }
    __syncthreads();

    const uint32_t* ws = (const uint32_t*)w_s;
    const uint32_t* as = (const uint32_t*)a_s;

    float c[8][4];
    #pragma unroll
    for (int j = 0; j < 8; j++)
        #pragma unroll
        for (int t = 0; t < 4; t++) c[j][t] = 0.f;

    #pragma unroll
    for (int ks = 0; ks < 16; ks++) {
        uint32_t a[4];
        int r0 = (wid * 16 + g) * PW_STRIDE + ks * 8 + q;
        a[0] = ws[r0];
        a[1] = ws[r0 + 8 * PW_STRIDE];
        a[2] = ws[r0 + 4];
        a[3] = ws[r0 + 8 * PW_STRIDE + 4];
        #pragma unroll
        for (int j = 0; j < 8; j++) {
            uint32_t b0 = as[(ks * 8 + q)     * PA_STRIDE + j * 8 + g];
            uint32_t b1 = as[(ks * 8 + q + 4) * PA_STRIDE + j * 8 + g];
            mma_tf32(c[j], a, b0, b1);
        }
    }

    #pragma unroll
    for (int j = 0; j < 8; j++) {
        int oc  = wid * 16 + g;
        int col = n0 + j * 8 + 2 * q;
        float* p = out + (size_t)(b * 256 + 128 + oc) * N_SP;
        *(float2*)&p[col]            = make_float2(c[j][0], c[j][1]);
        *(float2*)&p[8 * N_SP + col] = make_float2(c[j][2], c[j][3]);
    }
}

// ---------------------------------------------------------------------------
extern "C" void kernel_launch(void* const* d_in, const int* in_sizes, int n_in,
                              void* d_out, int out_size)
{
    const float* x      = (const float*)d_in[0];
    const float* w_init = (const float*)d_in[1];
    const float* w_qkv  = (const float*)d_in[2];
    const float* w_out  = (const float*)d_in[3];
    float* out = (float*)d_out;

    const int conv_smem = (XS_U32 + 2 * WCHUNK) * 4;               // 104448 B
    const int attn_smem = (2 * KBUF) * 4 + (2 * VBUF) * 4;         // 26112 B
    const int proj_smem = (128 * PW_STRIDE + 128 * PA_STRIDE) * 4; // 104448 B
    cudaFuncSetAttribute(conv_mma_kernel,
                         cudaFuncAttributeMaxDynamicSharedMemorySize, conv_smem);
    cudaFuncSetAttribute(attn_mma_kernel,
                         cudaFuncAttributeMaxDynamicSharedMemorySize, attn_smem);
    cudaFuncSetAttribute(proj_mma_kernel,
                         cudaFuncAttributeMaxDynamicSharedMemorySize, proj_smem);

    wprep_kernel<<<288, 1024>>>(w_init, w_qkv);

    dim3 cg(4, 16, 4);
    conv_mma_kernel<<<cg, 256, conv_smem>>>(x, out);

    dim3 ag(18, 8, 4);
    attn_mma_kernel<<<ag, 256, attn_smem>>>();

    dim3 pg(36, 4);
    proj_mma_kernel<<<pg, 256, proj_smem>>>(w_out, out);
}

// round 16
// speedup vs baseline: 1.5193x; 1.0574x over previous
#include <cuda_runtime.h>
#include <cuda_bf16.h>
#include <cuda_fp16.h>
#include <cstdint>

// Scratch (allocation-free rule: __device__ globals)
__device__ float    g_qkv[4 * 384 * 2304];  // (b,384,N): q=0..127, k=128..255
__device__ uint32_t g_vbf[4 * 128 * 1152];  // V packed f16x2 key-pairs: [b][vch][keypair]
__device__ float    g_attn[4 * 128 * 2304]; // (b,8,N,16) contiguous == (b,128,N) reinterpret
__device__ uint32_t g_w[9 * 2 * 4 * 4096];  // conv weights fp16x2: [tap][half][ocg][4096]

#define N_SP 2304   // 48*48

__device__ __forceinline__ uint32_t to_tf32(float f) {
    uint32_t t;
    asm("cvt.rna.tf32.f32 %0, %1;" : "=r"(t) : "f"(f));
    return t;
}

__device__ __forceinline__ uint32_t pack_f16(float hi, float lo) {
    uint32_t r;
    asm("cvt.rn.f16x2.f32 %0, %1, %2;" : "=r"(r) : "f"(hi), "f"(lo));
    return r;
}

__device__ __forceinline__ uint32_t ex2_f16x2(uint32_t v) {
    uint32_t r;
    asm("ex2.approx.f16x2 %0, %1;" : "=r"(r) : "r"(v));
    return r;
}

__device__ __forceinline__ uint32_t hadd2(uint32_t a, uint32_t b) {
    uint32_t r;
    asm("add.rn.f16x2 %0, %1, %2;" : "=r"(r) : "r"(a), "r"(b));
    return r;
}

__device__ __forceinline__ void mma_tf32(float c[4], const uint32_t a[4],
                                         uint32_t b0, uint32_t b1)
{
    asm volatile(
        "mma.sync.aligned.m16n8k8.row.col.f32.tf32.tf32.f32 "
        "{%0,%1,%2,%3}, {%4,%5,%6,%7}, {%8,%9}, {%0,%1,%2,%3};"
        : "+f"(c[0]), "+f"(c[1]), "+f"(c[2]), "+f"(c[3])
        : "r"(a[0]), "r"(a[1]), "r"(a[2]), "r"(a[3]), "r"(b0), "r"(b1));
}

__device__ __forceinline__ void mma_f16v(float c[4], uint4 a,
                                         uint32_t b0, uint32_t b1)
{
    asm volatile(
        "mma.sync.aligned.m16n8k16.row.col.f32.f16.f16.f32 "
        "{%0,%1,%2,%3}, {%4,%5,%6,%7}, {%8,%9}, {%0,%1,%2,%3};"
        : "+f"(c[0]), "+f"(c[1]), "+f"(c[2]), "+f"(c[3])
        : "r"(a.x), "r"(a.y), "r"(a.z), "r"(a.w), "r"(b0), "r"(b1));
}

__device__ __forceinline__ void mma_f16a(float c[4], const uint32_t a[4],
                                         uint32_t b0, uint32_t b1)
{
    asm volatile(
        "mma.sync.aligned.m16n8k16.row.col.f32.f16.f16.f32 "
        "{%0,%1,%2,%3}, {%4,%5,%6,%7}, {%8,%9}, {%0,%1,%2,%3};"
        : "+f"(c[0]), "+f"(c[1]), "+f"(c[2]), "+f"(c[3])
        : "r"(a[0]), "r"(a[1]), "r"(a[2]), "r"(a[3]), "r"(b0), "r"(b1));
}

__device__ __forceinline__ void cp_async16(uint32_t smem_addr, const void* gptr) {
    asm volatile("cp.async.cg.shared.global [%0], [%1], 16;"
                 :: "r"(smem_addr), "l"(gptr));
}
#define CP_COMMIT() asm volatile("cp.async.commit_group;" ::: "memory")
#define CP_WAIT0()  asm volatile("cp.async.wait_group 0;" ::: "memory")

// ---------------------------------------------------------------------------
// Kernel 0: pack conv weights as fp16x2 ic-pairs in m16n8k16 A-frag order.
// ---------------------------------------------------------------------------
__global__ __launch_bounds__(1024) void wprep_kernel(
    const float* __restrict__ w_init, const float* __restrict__ w_qkv)
{
    int idx = blockIdx.x * 1024 + threadIdx.x;   // 294912 total
    int e     = idx & 3;
    int lane  = (idx >> 2) & 31;
    int icclo = (idx >> 7) & 3;
    int ob    = (idx >> 9) & 7;
    int ocg   = (idx >> 12) & 3;
    int half  = (idx >> 14) & 1;
    int tap   = idx >> 15;
    int g = lane >> 2, q = lane & 3;
    int icc = half * 4 + icclo;
    int oc = ocg * 128 + ob * 16 + g + (e & 1) * 8;
    int ic = icc * 16 + 2 * q + ((e >> 1) & 1) * 8;
    float w0, w1;
    if (oc < 128) {
        w0 = w_init[(oc * 128 + ic) * 9 + tap];
        w1 = w_init[(oc * 128 + ic + 1) * 9 + tap];
    } else {
        w0 = w_qkv[((oc - 128) * 128 + ic) * 9 + tap];
        w1 = w_qkv[((oc - 128) * 128 + ic + 1) * 9 + tap];
    }
    g_w[idx] = pack_f16(w1, w0);
}

// ---------------------------------------------------------------------------
// Kernel 1: 3x3 circular conv, fp16 mma implicit GEMM (R15 config, frozen).
// THREE output rows per CTA -> 256 CTAs, 2 CTAs/SM.
// ---------------------------------------------------------------------------
#define XS_STRIDE 56
#define XS_U32 (5 * 64 * XS_STRIDE)       // 17920 u32 = 71680 B
#define WCHUNK 4096

__global__ __launch_bounds__(256, 2) void conv_mma_kernel(
    const float* __restrict__ x, float* __restrict__ out)
{
    extern __shared__ uint32_t smu[];
    uint32_t* x_s = smu;                  // [5 rows][64 icpair][56]
    uint32_t* w_s = smu + XS_U32;         // [2][4096]

    const int b   = blockIdx.z;
    const int rp  = blockIdx.y;
    const int ocg = blockIdx.x;
    const int tid = threadIdx.x;
    const int wid = tid >> 5, lane = tid & 31;
    const int warp_m = wid & 3;
    const int warp_n = wid >> 2;
    const int g = lane >> 2, q = lane & 3;

    int rowj[9], colj[9];
    #pragma unroll
    for (int jj = 0; jj < 9; jj++) {
        int flat = warp_n * 72 + jj * 8;
        rowj[jj] = flat / 48;
        colj[jj] = flat - rowj[jj] * 48;
    }

    const uint32_t ws_u32 = (uint32_t)__cvta_generic_to_shared(w_s);

    auto stage_w = [&](int c) {
        const float4* src = (const float4*)(g_w + ((size_t)c * 4 + ocg) * WCHUNK);
        uint32_t dst = ws_u32 + (uint32_t)(c & 1) * (WCHUNK * 4);
        #pragma unroll
        for (int i = 0; i < 4; i++) {
            int e4 = tid + i * 256;
            cp_async16(dst + e4 * 16, src + e4);
        }
    };

    stage_w(0); CP_COMMIT();

    #pragma unroll
    for (int li = 0; li < 40; li++) {
        int l = wid + li * 8;
        int r = l >> 6, icp = l & 63;
        int srow = (3 * rp - 1 + r + 48) % 48;
        const float* s0 = x + ((b * 128 + 2 * icp) * 48 + srow) * 48;
        const float* s1 = s0 + 2304;
        uint32_t* dst = &x_s[(r * 64 + icp) * XS_STRIDE];
        dst[2 + lane] = pack_f16(s1[lane], s0[lane]);
        if (lane < 16)
            dst[34 + lane] = pack_f16(s1[32 + lane], s0[32 + lane]);
        else if (lane == 16)
            dst[1]  = pack_f16(s1[47], s0[47]);
        else if (lane == 17)
            dst[50] = pack_f16(s1[0], s0[0]);
    }

    float c_acc[2][9][4];
    #pragma unroll
    for (int mi = 0; mi < 2; mi++)
        #pragma unroll
        for (int j = 0; j < 9; j++)
            #pragma unroll
            for (int t = 0; t < 4; t++) c_acc[mi][j][t] = 0.f;

    for (int c = 0; c < 18; c++) {
        CP_WAIT0();
        __syncthreads();
        if (c < 17) { stage_w(c + 1); CP_COMMIT(); }

        const int tap = c >> 1, half = c & 1;
        const int dr = tap / 3 - 1, dc = tap % 3 - 1;
        const uint4* wbuf = (const uint4*)(w_s + (c & 1) * WCHUNK);

        #pragma unroll
        for (int icclo = 0; icclo < 4; icclo++) {
            const int icc = half * 4 + icclo;
            uint4 a0 = wbuf[((warp_m * 2 + 0) * 4 + icclo) * 32 + lane];
            uint4 a1 = wbuf[((warp_m * 2 + 1) * 4 + icclo) * 32 + lane];
            #pragma unroll
            for (int jj = 0; jj < 9; jj++) {
                const uint32_t* xrow = x_s + (rowj[jj] + dr + 1) * 64 * XS_STRIDE;
                int cb = colj[jj] + dc + 2 + g;
                uint32_t b0 = xrow[(icc * 8 + q)     * XS_STRIDE + cb];
                uint32_t b1 = xrow[(icc * 8 + q + 4) * XS_STRIDE + cb];
                mma_f16v(c_acc[0][jj], a0, b0, b1);
                mma_f16v(c_acc[1][jj], a1, b0, b1);
            }
        }
    }

    #pragma unroll
    for (int mi = 0; mi < 2; mi++) {
        int oc_l = ocg * 128 + warp_m * 32 + mi * 16 + g;
        if (oc_l < 384) {
            float* p = (oc_l < 128)
                ? out   + (size_t)(b * 256 + oc_l) * N_SP
                : g_qkv + (size_t)(b * 384 + oc_l - 128) * N_SP;
            float* p8 = p + 8 * N_SP;
            #pragma unroll
            for (int jj = 0; jj < 9; jj++) {
                int spat = (3 * rp + rowj[jj]) * 48 + colj[jj] + 2 * q;
                *(float2*)&p [spat] = make_float2(c_acc[mi][jj][0], c_acc[mi][jj][1]);
                *(float2*)&p8[spat] = make_float2(c_acc[mi][jj][2], c_acc[mi][jj][3]);
            }
        } else {
            int vch = oc_l - 384;
            uint32_t* v0 = g_vbf + (size_t)(b * 128 + vch) * 1152;
            uint32_t* v8 = v0 + 8 * 1152;
            #pragma unroll
            for (int jj = 0; jj < 9; jj++) {
                int kp = (3 * rp + rowj[jj]) * 24 + (colj[jj] >> 1) + q;
                v0[kp] = pack_f16(c_acc[mi][jj][1], c_acc[mi][jj][0]);
                v8[kp] = pack_f16(c_acc[mi][jj][3], c_acc[mi][jj][2]);
            }
        }
    }
}

// ---------------------------------------------------------------------------
// Kernel 2: flash attention, TWO q-tiles (256 queries) per CTA.
// Grid 9x8x4 = 288 CTAs = one full wave at 2 CTAs/SM; K/V staging reused
// across both q-tiles. S: tf32 mma; softmax ex2.f16x2 -> f16 PV mma.
// ---------------------------------------------------------------------------
#define KS_STRIDE 136
#define VS2_STRIDE 68
#define KBUF (16 * KS_STRIDE)
#define VBUF (16 * VS2_STRIDE)

__global__ __launch_bounds__(256, 2) void attn_mma_kernel()
{
    extern __shared__ float sm[];
    float*    k_s = sm;                          // [2][16][136]
    uint32_t* v_s = (uint32_t*)(sm + 2 * KBUF);  // [2][16][68]

    const int b = blockIdx.z, h = blockIdx.y, qt = blockIdx.x;
    const int tid = threadIdx.x, wid = tid >> 5, lane = tid & 31;
    const int g = lane >> 2, q = lane & 3;

    const float*    qptr = g_qkv + (size_t)(b * 384 + h * 16) * N_SP;
    const float*    kptr = g_qkv + (size_t)(b * 384 + 128 + h * 16) * N_SP;
    const uint32_t* vptr = g_vbf + (size_t)(b * 128 + h * 16) * 1152;

    const uint32_t ks_u32 = (uint32_t)__cvta_generic_to_shared(k_s);
    const uint32_t vs_u32 = (uint32_t)__cvta_generic_to_shared(v_s);

    auto stage = [&](int kt) {
        uint32_t buf = (uint32_t)(kt & 1);
        #pragma unroll
        for (int it = 0; it < 2; it++) {
            int i  = tid + it * 256;
            int ch = i >> 5, k4 = i & 31;
            cp_async16(ks_u32 + (buf * KBUF + ch * KS_STRIDE + k4 * 4) * 4,
                       kptr + ch * N_SP + kt * 128 + k4 * 4);
        }
        {
            int ch = tid >> 4, kp4 = tid & 15;
            cp_async16(vs_u32 + (buf * VBUF + ch * VS2_STRIDE + kp4 * 4) * 4,
                       vptr + ch * 1152 + kt * 64 + kp4 * 4);
        }
    };

    stage(0); CP_COMMIT();

    const float qscale = 0.25f * 1.4426950408889634f;
    // two q-tiles: queries qt*256 + wid*16 (+128 for tile 1)
    uint32_t qa[2][2][4];
    #pragma unroll
    for (int t2 = 0; t2 < 2; t2++) {
        const int qb = qt * 256 + t2 * 128 + wid * 16;
        #pragma unroll
        for (int s = 0; s < 2; s++) {
            qa[t2][s][0] = to_tf32(qptr[(s * 8 + q)     * N_SP + qb + g]     * qscale);
            qa[t2][s][1] = to_tf32(qptr[(s * 8 + q)     * N_SP + qb + g + 8] * qscale);
            qa[t2][s][2] = to_tf32(qptr[(s * 8 + q + 4) * N_SP + qb + g]     * qscale);
            qa[t2][s][3] = to_tf32(qptr[(s * 8 + q + 4) * N_SP + qb + g + 8] * qscale);
        }
    }

    float sum_g[2] = {0.f, 0.f}, sum_g8[2] = {0.f, 0.f};
    float o[2][2][4];
    #pragma unroll
    for (int t2 = 0; t2 < 2; t2++)
        #pragma unroll
        for (int nt = 0; nt < 2; nt++)
            #pragma unroll
            for (int t = 0; t < 4; t++) o[t2][nt][t] = 0.f;

    for (int kt = 0; kt < 18; kt++) {
        CP_WAIT0();
        __syncthreads();
        if (kt < 17) { stage(kt + 1); CP_COMMIT(); }

        const uint32_t* ks32 = (const uint32_t*)(k_s + (kt & 1) * KBUF);
        const uint32_t* vbuf = v_s + (kt & 1) * VBUF;

        uint32_t sg2[2] = {0, 0}, sg82[2] = {0, 0};

        #pragma unroll
        for (int kb = 0; kb < 8; kb++) {
            // preload shared K/V fragments once for both q-tiles
            uint32_t kb00[2], kb01[2], kb10[2], kb11[2];
            #pragma unroll
            for (int s = 0; s < 2; s++) {
                kb00[s] = ks32[(s * 8 + q)     * KS_STRIDE + kb * 16 + g];
                kb01[s] = ks32[(s * 8 + q + 4) * KS_STRIDE + kb * 16 + g];
                kb10[s] = ks32[(s * 8 + q)     * KS_STRIDE + kb * 16 + g + 8];
                kb11[s] = ks32[(s * 8 + q + 4) * KS_STRIDE + kb * 16 + g + 8];
            }
            uint32_t vb00 = vbuf[g * VS2_STRIDE + kb * 8 + q];
            uint32_t vb01 = vbuf[g * VS2_STRIDE + kb * 8 + q + 4];
            uint32_t vb10 = vbuf[(8 + g) * VS2_STRIDE + kb * 8 + q];
            uint32_t vb11 = vbuf[(8 + g) * VS2_STRIDE + kb * 8 + q + 4];

            #pragma unroll
            for (int t2 = 0; t2 < 2; t2++) {
                float cs0[4] = {0.f, 0.f, 0.f, 0.f};
                float cs1[4] = {0.f, 0.f, 0.f, 0.f};
                #pragma unroll
                for (int s = 0; s < 2; s++) {
                    mma_tf32(cs0, qa[t2][s], kb00[s], kb01[s]);
                    mma_tf32(cs1, qa[t2][s], kb10[s], kb11[s]);
                }

                uint32_t a[4];
                a[0] = ex2_f16x2(pack_f16(cs0[1], cs0[0]));
                a[1] = ex2_f16x2(pack_f16(cs0[3], cs0[2]));
                a[2] = ex2_f16x2(pack_f16(cs1[1], cs1[0]));
                a[3] = ex2_f16x2(pack_f16(cs1[3], cs1[2]));

                sg2[t2]  = hadd2(sg2[t2],  hadd2(a[0], a[2]));
                sg82[t2] = hadd2(sg82[t2], hadd2(a[1], a[3]));

                mma_f16a(o[t2][0], a, vb00, vb01);
                mma_f16a(o[t2][1], a, vb10, vb11);
            }
        }

        #pragma unroll
        for (int t2 = 0; t2 < 2; t2++) {
            float2 f0 = __half22float2(*reinterpret_cast<__half2*>(&sg2[t2]));
            float2 f1 = __half22float2(*reinterpret_cast<__half2*>(&sg82[t2]));
            sum_g[t2]  += f0.x + f0.y;
            sum_g8[t2] += f1.x + f1.y;
        }
    }

    #pragma unroll
    for (int t2 = 0; t2 < 2; t2++) {
        float sg = sum_g[t2], sg8 = sum_g8[t2];
        sg  += __shfl_xor_sync(0xffffffffu, sg, 1);
        sg  += __shfl_xor_sync(0xffffffffu, sg, 2);
        sg8 += __shfl_xor_sync(0xffffffffu, sg8, 1);
        sg8 += __shfl_xor_sync(0xffffffffu, sg8, 2);
        const float il = 1.f / sg, il8 = 1.f / sg8;

        const int qb = qt * 256 + t2 * 128 + wid * 16;
        const size_t nb = (size_t)(b * 8 + h) * N_SP;
        #pragma unroll
        for (int nt = 0; nt < 2; nt++) {
            float* d0 = g_attn + (nb + qb + g)     * 16 + nt * 8 + 2 * q;
            float* d8 = g_attn + (nb + qb + g + 8) * 16 + nt * 8 + 2 * q;
            *(float2*)d0 = make_float2(o[t2][nt][0] * il,  o[t2][nt][1] * il);
            *(float2*)d8 = make_float2(o[t2][nt][2] * il8, o[t2][nt][3] * il8);
        }
    }
}

// ---------------------------------------------------------------------------
// Kernel 3: 1x1 projection, tf32 mma (frozen R13 config)
// ---------------------------------------------------------------------------
#define PW_STRIDE 132
#define PA_STRIDE 72

__global__ __launch_bounds__(256) void proj_mma_kernel(
    const float* __restrict__ w_out, float* __restrict__ out)
{
    extern __shared__ float smf[];
    float* w_s = smf;
    float* a_s = smf + 128 * PW_STRIDE;

    const int b  = blockIdx.y;
    const int n0 = blockIdx.x * 64;
    const int tid = threadIdx.x, wid = tid >> 5, lane = tid & 31;
    const int g = lane >> 2, q = lane & 3;

    const float4* wsrc = (const float4*)w_out;
    #pragma unroll
    for (int i = 0; i < 16; i++) {
        int e4 = tid + i * 256;
        int oc = e4 >> 5, ic4 = e4 & 31;
        *(float4*)&w_s[oc * PW_STRIDE + ic4 * 4] = wsrc[e4];
    }
    #pragma unroll
    for (int i = 0; i < 8; i++) {
        int e4 = tid + i * 256;
        int ic = e4 >> 4, c4 = e4 & 15;
        *(float4*)&a_s[ic * PA_STRIDE + c4 * 4] =
            *(const float4*)&g_attn[(size_t)(b * 128 + ic) * N_SP + n0 + c4 * 4];
    }
    __syncthreads();

    const uint32_t* ws = (const uint32_t*)w_s;
    const uint32_t* as = (const uint32_t*)a_s;

    float c[8][4];
    #pragma unroll
    for (int j = 0; j < 8; j++)
        #pragma unroll
        for (int t = 0; t < 4; t++) c[j][t] = 0.f;

    #pragma unroll
    for (int ks = 0; ks < 16; ks++) {
        uint32_t a[4];
        int r0 = (wid * 16 + g) * PW_STRIDE + ks * 8 + q;
        a[0] = ws[r0];
        a[1] = ws[r0 + 8 * PW_STRIDE];
        a[2] = ws[r0 + 4];
        a[3] = ws[r0 + 8 * PW_STRIDE + 4];
        #pragma unroll
        for (int j = 0; j < 8; j++) {
            uint32_t b0 = as[(ks * 8 + q)     * PA_STRIDE + j * 8 + g];
            uint32_t b1 = as[(ks * 8 + q + 4) * PA_STRIDE + j * 8 + g];
            mma_tf32(c[j], a, b0, b1);
        }
    }

    #pragma unroll
    for (int j = 0; j < 8; j++) {
        int oc  = wid * 16 + g;
        int col = n0 + j * 8 + 2 * q;
        float* p = out + (size_t)(b * 256 + 128 + oc) * N_SP;
        *(float2*)&p[col]            = make_float2(c[j][0], c[j][1]);
        *(float2*)&p[8 * N_SP + col] = make_float2(c[j][2], c[j][3]);
    }
}

// ---------------------------------------------------------------------------
extern "C" void kernel_launch(void* const* d_in, const int* in_sizes, int n_in,
                              void* d_out, int out_size)
{
    const float* x      = (const float*)d_in[0];
    const float* w_init = (const float*)d_in[1];
    const float* w_qkv  = (const float*)d_in[2];
    const float* w_out  = (const float*)d_in[3];
    float* out = (float*)d_out;

    const int conv_smem = (XS_U32 + 2 * WCHUNK) * 4;               // 104448 B
    const int attn_smem = (2 * KBUF) * 4 + (2 * VBUF) * 4;         // 26112 B
    const int proj_smem = (128 * PW_STRIDE + 128 * PA_STRIDE) * 4; // 104448 B
    cudaFuncSetAttribute(conv_mma_kernel,
                         cudaFuncAttributeMaxDynamicSharedMemorySize, conv_smem);
    cudaFuncSetAttribute(attn_mma_kernel,
                         cudaFuncAttributeMaxDynamicSharedMemorySize, attn_smem);
    cudaFuncSetAttribute(proj_mma_kernel,
                         cudaFuncAttributeMaxDynamicSharedMemorySize, proj_smem);

    wprep_kernel<<<288, 1024>>>(w_init, w_qkv);

    dim3 cg(4, 16, 4);
    conv_mma_kernel<<<cg, 256, conv_smem>>>(x, out);

    dim3 ag(9, 8, 4);
    attn_mma_kernel<<<ag, 256, attn_smem>>>();

    dim3 pg(36, 4);
    proj_mma_kernel<<<pg, 256, proj_smem>>>(w_out, out);
}